// round 10
// baseline (speedup 1.0000x reference)
#include <cuda_runtime.h>
#include <cuda_bf16.h>

#define NMAX   50016
#define EMAX   800000
#define NF     128
#define HH     256
#define OUT2   128
#define NHEADS 4
#define NEG    0.2f

// ---- scratch ----
__device__ float g_h1  [(size_t)NMAX * HH];
__device__ float g_agg1[(size_t)NMAX * HH];
__device__ float g_h2  [(size_t)NMAX * OUT2];
__device__ float g_as1[NMAX * NHEADS];
__device__ float g_ad1[NMAX * NHEADS];
__device__ float g_as2[NMAX];
__device__ float g_ad2[NMAX];
__device__ float g_va1[NF * 8];
__device__ float g_wa2[HH * 2];
__device__ int   g_is64;
// CSR
__device__ int   g_cnt [NMAX + 1];
__device__ int   g_off [NMAX + 1];
__device__ int   g_cur [NMAX + 1];
__device__ int   g_bsum[64];
__device__ int   g_boff[64];
__device__ int   g_csrc[EMAX];
__device__ float g_w1  [(size_t)EMAX * NHEADS];

__device__ __forceinline__ void load_edge(const void* ei, int E, int i,
                                          int& s, int& d) {
    if (g_is64) {
        const long long* p = (const long long*)ei;
        s = (int)p[i]; d = (int)p[(size_t)E + i];
    } else {
        const int* p = (const int*)ei;
        s = p[i]; d = p[E + i];
    }
}

__device__ __forceinline__ float lrelu_exp(float v) {
    v = v > 0.f ? v : NEG * v;
    return __expf(v);
}

#define MMA_BF16(c0,c1,c2,c3,a0,a1,a2,a3,b0,b1) \
    asm("mma.sync.aligned.m16n8k16.row.col.f32.bf16.bf16.f32 " \
        "{%0,%1,%2,%3}, {%4,%5,%6,%7}, {%8,%9}, {%0,%1,%2,%3};" \
        : "+f"(c0), "+f"(c1), "+f"(c2), "+f"(c3) \
        : "r"(a0), "r"(a1), "r"(a2), "r"(a3), "r"(b0), "r"(b1))

#define LDSM4(R0,R1,R2,R3,A) \
    asm volatile("ldmatrix.sync.aligned.m8n8.x4.shared.b16 {%0,%1,%2,%3}, [%4];" \
        : "=r"(R0), "=r"(R1), "=r"(R2), "=r"(R3) : "r"(A))
#define LDSM2(R0,R1,A) \
    asm volatile("ldmatrix.sync.aligned.m8n8.x2.shared.b16 {%0,%1}, [%2];" \
        : "=r"(R0), "=r"(R1) : "r"(A))

__device__ __forceinline__ unsigned sm_u32(const void* p) {
    return (unsigned)__cvta_generic_to_shared(p);
}

__device__ __forceinline__ unsigned bf16_hi_pack(float a, float b) {
    unsigned ua = (unsigned)__bfloat16_as_ushort(__float2bfloat16(a));
    unsigned ub = (unsigned)__bfloat16_as_ushort(__float2bfloat16(b));
    return ua | (ub << 16);
}
__device__ __forceinline__ unsigned bf16_lo_pack(float a, float b) {
    float ra = a - __bfloat162float(__float2bfloat16(a));
    float rb = b - __bfloat162float(__float2bfloat16(b));
    return bf16_hi_pack(ra, rb);
}
__device__ __forceinline__ __nv_bfloat16 bf16_lo(float a) {
    return __float2bfloat16(a - __bfloat162float(__float2bfloat16(a)));
}

// ============ KZ: dtype probe + zero counts ============
__global__ void kz(const int* ei32, int E, int n) {
    int i = blockIdx.x * 1024 + threadIdx.x;
    if (i <= n) g_cnt[i] = 0;
    if (blockIdx.x == 0) {
        __shared__ int flag;
        if (threadIdx.x == 0) flag = 0;
        __syncthreads();
        for (int j = threadIdx.x; j < 2048; j += 1024) {
            int idx = 2 * j + 1;
            if (idx < 2 * E && ei32[idx] != 0) flag = 1;
        }
        __syncthreads();
        if (threadIdx.x == 0) g_is64 = (flag == 0);
    }
}

// ============ KC2: count in-degrees ============
__global__ void kc2_count(const void* __restrict__ ei, int E) {
    int i = blockIdx.x * blockDim.x + threadIdx.x;
    if (i >= E) return;
    int s, d; load_edge(ei, E, i, s, d);
    atomicAdd(&g_cnt[d], 1);
}

// ============ KV: attention-vector precomputes ============
__global__ void kv(const float* __restrict__ W1, const float* __restrict__ a_s1,
                   const float* __restrict__ a_d1, const float* __restrict__ W2,
                   const float* __restrict__ a_s2, const float* __restrict__ a_d2) {
    int t = blockIdx.x * 256 + threadIdx.x;
    if (t < NF * 8) {
        int k = t >> 3, o = t & 7, h = o & 3;
        const float* a = (o < 4 ? a_s1 : a_d1) + h * 64;
        const float* w = W1 + (size_t)k * HH + h * 64;
        float s = 0.f;
        #pragma unroll 8
        for (int c = 0; c < 64; c++) s += w[c] * a[c];
        g_va1[t] = s;
    } else if (t < NF * 8 + HH * 2) {
        int q = t - NF * 8;
        int k = q >> 1, o = q & 1;
        const float* a = o ? a_d2 : a_s2;
        const float* w = W2 + (size_t)k * OUT2;
        float s = 0.f;
        #pragma unroll 8
        for (int c = 0; c < OUT2; c++) s += w[c] * a[c];
        g_wa2[q] = s;
    }
}

// ============ K1: h1 = x @ W1  (bf16-split MMA + ldmatrix) ============
#define K1_PAD   136
#define K1_XSZ   (64 * K1_PAD)
#define K1_SMEM  (4 * K1_XSZ * 2)
__global__ void k1_gemm1(const float* __restrict__ x, const float* __restrict__ W1,
                         int n_nodes) {
    extern __shared__ __nv_bfloat16 smb[];
    __nv_bfloat16* Xhi = smb;
    __nv_bfloat16* Xlo = smb + K1_XSZ;
    __nv_bfloat16* Whi = smb + 2 * K1_XSZ;
    __nv_bfloat16* Wlo = smb + 3 * K1_XSZ;
    const int n0 = blockIdx.x * 64;
    const int c0 = blockIdx.y * 64;
    const int tid = threadIdx.x;          // 256

    #pragma unroll
    for (int r = 0; r < 8; r++) {
        int i = tid + r * 256;
        int nn = i >> 5, k4 = i & 31;
        int g = n0 + nn;
        float4 v = make_float4(0.f, 0.f, 0.f, 0.f);
        if (g < n_nodes) v = *reinterpret_cast<const float4*>(x + (size_t)g * NF + 4 * k4);
        uint2 hp, lp;
        hp.x = bf16_hi_pack(v.x, v.y); hp.y = bf16_hi_pack(v.z, v.w);
        lp.x = bf16_lo_pack(v.x, v.y); lp.y = bf16_lo_pack(v.z, v.w);
        *reinterpret_cast<uint2*>(&Xhi[nn * K1_PAD + 4 * k4]) = hp;
        *reinterpret_cast<uint2*>(&Xlo[nn * K1_PAD + 4 * k4]) = lp;
    }
    #pragma unroll
    for (int r = 0; r < 8; r++) {
        int i = tid + r * 256;
        int k = i >> 4, c4 = i & 15;
        float4 w = *reinterpret_cast<const float4*>(W1 + (size_t)k * HH + c0 + 4 * c4);
        int cb = 4 * c4;
        Whi[(cb + 0) * K1_PAD + k] = __float2bfloat16(w.x);
        Whi[(cb + 1) * K1_PAD + k] = __float2bfloat16(w.y);
        Whi[(cb + 2) * K1_PAD + k] = __float2bfloat16(w.z);
        Whi[(cb + 3) * K1_PAD + k] = __float2bfloat16(w.w);
        Wlo[(cb + 0) * K1_PAD + k] = bf16_lo(w.x);
        Wlo[(cb + 1) * K1_PAD + k] = bf16_lo(w.y);
        Wlo[(cb + 2) * K1_PAD + k] = bf16_lo(w.z);
        Wlo[(cb + 3) * K1_PAD + k] = bf16_lo(w.w);
    }
    __syncthreads();

    const int wid = tid >> 5, lane = tid & 31;
    const int wr = (wid >> 1) * 16;
    const int wc = (wid & 1) * 32;
    const int gq = lane >> 2, tg = lane & 3;

    // ldmatrix base addresses (byte offsets within smem)
    const int arow = wr + (lane & 15);
    const int ak   = (lane >> 4) * 8;
    unsigned aAhi = sm_u32(Xhi + arow * K1_PAD + ak);
    unsigned aAlo = sm_u32(Xlo + arow * K1_PAD + ak);
    const int brow_off = lane & 7;
    const int bk = ((lane >> 3) & 1) * 8;
    unsigned aBhi[4], aBlo[4];
    #pragma unroll
    for (int ns = 0; ns < 4; ns++) {
        int brow = wc + ns * 8 + brow_off;
        aBhi[ns] = sm_u32(Whi + brow * K1_PAD + bk);
        aBlo[ns] = sm_u32(Wlo + brow * K1_PAD + bk);
    }

    float C[4][4] = {};
    #pragma unroll
    for (int ks = 0; ks < 8; ks++) {
        const unsigned koff = ks * 32;    // 16 bf16 = 32 bytes
        unsigned ah0, ah1, ah2, ah3, al0, al1, al2, al3;
        LDSM4(ah0, ah1, ah2, ah3, aAhi + koff);
        LDSM4(al0, al1, al2, al3, aAlo + koff);
        #pragma unroll
        for (int ns = 0; ns < 4; ns++) {
            unsigned bh0, bh1, bl0, bl1;
            LDSM2(bh0, bh1, aBhi[ns] + koff);
            LDSM2(bl0, bl1, aBlo[ns] + koff);
            MMA_BF16(C[ns][0], C[ns][1], C[ns][2], C[ns][3],
                     ah0, ah1, ah2, ah3, bh0, bh1);
            MMA_BF16(C[ns][0], C[ns][1], C[ns][2], C[ns][3],
                     ah0, ah1, ah2, ah3, bl0, bl1);
            MMA_BF16(C[ns][0], C[ns][1], C[ns][2], C[ns][3],
                     al0, al1, al2, al3, bh0, bh1);
        }
    }
    #pragma unroll
    for (int ns = 0; ns < 4; ns++) {
        int col = c0 + wc + ns * 8 + 2 * tg;
        int r0 = n0 + wr + gq;
        if (r0 < n_nodes)
            *reinterpret_cast<float2*>(g_h1 + (size_t)r0 * HH + col) =
                make_float2(C[ns][0], C[ns][1]);
        if (r0 + 8 < n_nodes)
            *reinterpret_cast<float2*>(g_h1 + (size_t)(r0 + 8) * HH + col) =
                make_float2(C[ns][2], C[ns][3]);
    }
}

// ============ KS1: layer-1 logits ============
__global__ void ks_alpha1(const float* __restrict__ x, int n_nodes) {
    __shared__ float xv[32][NF];
    __shared__ float sva[NF * 8];
    const int n0 = blockIdx.x * 32;
    const int tid = threadIdx.x;      // 256
    for (int i = tid; i < NF * 8; i += 256) sva[i] = g_va1[i];
    #pragma unroll
    for (int r = 0; r < 4; r++) {
        int i = tid + r * 256;
        int nn = i >> 5, k4 = i & 31;
        int g = n0 + nn;
        float4 v = make_float4(0.f, 0.f, 0.f, 0.f);
        if (g < n_nodes) v = *reinterpret_cast<const float4*>(x + (size_t)g * NF + 4 * k4);
        *reinterpret_cast<float4*>(&xv[nn][4 * k4]) = v;
    }
    __syncthreads();
    int nn = tid >> 3, o = tid & 7;
    int g = n0 + nn;
    float s = 0.f;
    #pragma unroll 8
    for (int k = 0; k < NF; k++) s += xv[nn][k] * sva[k * 8 + o];
    if (g < n_nodes) {
        if (o < 4) g_as1[g * 4 + o] = s;
        else       g_ad1[g * 4 + o - 4] = s;
    }
}

// ============ scan ============
__global__ void s1_scan(int n) {
    __shared__ int sd[1024];
    int tid = threadIdx.x;
    int i = blockIdx.x * 1024 + tid;
    int v = (i < n) ? g_cnt[i] : 0;
    sd[tid] = v;
    __syncthreads();
    #pragma unroll
    for (int off = 1; off < 1024; off <<= 1) {
        int t = (tid >= off) ? sd[tid - off] : 0;
        __syncthreads();
        sd[tid] += t;
        __syncthreads();
    }
    if (i < n) g_off[i] = sd[tid] - v;
    if (tid == 1023) g_bsum[blockIdx.x] = sd[1023];
}
__global__ void s2_scan(int nb) {
    if (threadIdx.x == 0) {
        int acc = 0;
        for (int b = 0; b < nb; b++) { int t = g_bsum[b]; g_boff[b] = acc; acc += t; }
    }
}
__global__ void s3_scan(int n, int E) {
    int i = blockIdx.x * 1024 + threadIdx.x;
    if (i < n) {
        int v = g_off[i] + g_boff[blockIdx.x];
        g_off[i] = v;
        g_cur[i] = v;
    }
    if (i == 0) g_off[n] = E;
}

// ============ KC3W1: CSR fill + layer-1 softmax numerators ============
__global__ void kc3w1(const void* __restrict__ ei, int E) {
    int i = blockIdx.x * blockDim.x + threadIdx.x;
    if (i >= E) return;
    int s, d; load_edge(ei, E, i, s, d);
    int p = atomicAdd(&g_cur[d], 1);
    g_csrc[p] = s;
    float4 as = *reinterpret_cast<const float4*>(g_as1 + 4 * s);
    float4 ad = *reinterpret_cast<const float4*>(g_ad1 + 4 * d);
    float4 w;
    w.x = lrelu_exp(as.x + ad.x);
    w.y = lrelu_exp(as.y + ad.y);
    w.z = lrelu_exp(as.z + ad.z);
    w.w = lrelu_exp(as.w + ad.w);
    *reinterpret_cast<float4*>(g_w1 + (size_t)p * 4) = w;
}

// ============ KA1: gather aggregation, layer 1 ============
__global__ void ka1(int n_nodes) {
    __shared__ int   ssrc[128];
    __shared__ float sw[128 * 4];
    const int d = blockIdx.x;
    const int j = threadIdx.x;    // 256
    const int h = j >> 6;
    float w0 = lrelu_exp(g_as1[d * NHEADS + h] + g_ad1[d * NHEADS + h]);
    float den = w0;
    float acc = w0 * g_h1[(size_t)d * HH + j];
    const int pB = g_off[d], pE = g_off[d + 1];
    for (int p0 = pB; p0 < pE; p0 += 128) {
        int np = min(128, pE - p0);
        __syncthreads();
        if (j < np) {
            ssrc[j] = g_csrc[p0 + j];
        } else if (j >= 128 && j - 128 < np) {
            int e = j - 128;
            *reinterpret_cast<float4*>(&sw[4 * e]) =
                *reinterpret_cast<const float4*>(g_w1 + (size_t)(p0 + e) * 4);
        }
        __syncthreads();
        #pragma unroll 4
        for (int e = 0; e < np; e++) {
            int s = ssrc[e];
            float wp = sw[4 * e + h];
            den += wp;
            acc += wp * g_h1[(size_t)s * HH + j];
        }
    }
    g_agg1[(size_t)d * HH + j] = acc / den;
}

// ============ K4: h2 = elu(agg1+b1) @ W2 (bf16-split MMA) + layer-2 logits ====
// Block: 64 rows x 128 cols, 2 k-chunks of 128.
// smem bf16: Xhi/Xlo[64][136], Whi/Wlo[128][136]; + swa[512] floats
#define K4_PAD   136
#define K4_XSZ   (64 * K4_PAD)
#define K4_WSZ   (128 * K4_PAD)
#define K4_SMEM  ((2 * K4_XSZ + 2 * K4_WSZ) * 2 + HH * 2 * 4)
__global__ void k4_gemm2(const float* __restrict__ W2, const float* __restrict__ b1,
                         int n_nodes) {
    extern __shared__ __nv_bfloat16 smb[];
    __nv_bfloat16* Xhi = smb;
    __nv_bfloat16* Xlo = smb + K4_XSZ;
    __nv_bfloat16* Whi = smb + 2 * K4_XSZ;
    __nv_bfloat16* Wlo = smb + 2 * K4_XSZ + K4_WSZ;
    float* swa = reinterpret_cast<float*>(smb + 2 * K4_XSZ + 2 * K4_WSZ);
    const int n0 = blockIdx.x * 64;
    const int tid = threadIdx.x;          // 256
    for (int i = tid; i < HH * 2; i += 256) swa[i] = g_wa2[i];

    const int wid = tid >> 5, lane = tid & 31;
    const int wr = (wid >> 1) * 16;       // 0,16,32,48
    const int wc = (wid & 1) * 64;        // 0,64
    const int gq = lane >> 2, tg = lane & 3;

    const int arow = wr + (lane & 15);
    const int ak   = (lane >> 4) * 8;
    unsigned aAhi = sm_u32(Xhi + arow * K4_PAD + ak);
    unsigned aAlo = sm_u32(Xlo + arow * K4_PAD + ak);
    const int brow_off = lane & 7;
    const int bk = ((lane >> 3) & 1) * 8;

    float C[8][4] = {};
    float ls = 0.f;
    #pragma unroll
    for (int kc = 0; kc < 2; kc++) {
        const int kbase = kc * 128;
        __syncthreads();
        // stage X chunk: elu(agg1+b1), split hi/lo
        #pragma unroll
        for (int r = 0; r < 8; r++) {
            int i = tid + r * 256;
            int nn = i >> 5, k4 = i & 31;
            int g = n0 + nn;
            float4 v = make_float4(0.f, 0.f, 0.f, 0.f);
            if (g < n_nodes) {
                int kk = kbase + 4 * k4;
                v = *reinterpret_cast<const float4*>(g_agg1 + (size_t)g * HH + kk);
                float4 b = *reinterpret_cast<const float4*>(b1 + kk);
                v.x += b.x; v.y += b.y; v.z += b.z; v.w += b.w;
                v.x = v.x > 0.f ? v.x : expm1f(v.x);
                v.y = v.y > 0.f ? v.y : expm1f(v.y);
                v.z = v.z > 0.f ? v.z : expm1f(v.z);
                v.w = v.w > 0.f ? v.w : expm1f(v.w);
            }
            uint2 hp, lp;
            hp.x = bf16_hi_pack(v.x, v.y); hp.y = bf16_hi_pack(v.z, v.w);
            lp.x = bf16_lo_pack(v.x, v.y); lp.y = bf16_lo_pack(v.z, v.w);
            *reinterpret_cast<uint2*>(&Xhi[nn * K4_PAD + 4 * k4]) = hp;
            *reinterpret_cast<uint2*>(&Xlo[nn * K4_PAD + 4 * k4]) = lp;
        }
        // stage W chunk transposed: [col][k]
        #pragma unroll
        for (int r = 0; r < 16; r++) {
            int i = tid + r * 256;        // 4096 tasks: 128 k x 32 col4
            int k = i >> 5, c4 = i & 31;
            float4 w = *reinterpret_cast<const float4*>(
                W2 + (size_t)(kbase + k) * OUT2 + 4 * c4);
            int cb = 4 * c4;
            Whi[(cb + 0) * K4_PAD + k] = __float2bfloat16(w.x);
            Whi[(cb + 1) * K4_PAD + k] = __float2bfloat16(w.y);
            Whi[(cb + 2) * K4_PAD + k] = __float2bfloat16(w.z);
            Whi[(cb + 3) * K4_PAD + k] = __float2bfloat16(w.w);
            Wlo[(cb + 0) * K4_PAD + k] = bf16_lo(w.x);
            Wlo[(cb + 1) * K4_PAD + k] = bf16_lo(w.y);
            Wlo[(cb + 2) * K4_PAD + k] = bf16_lo(w.z);
            Wlo[(cb + 3) * K4_PAD + k] = bf16_lo(w.w);
        }
        __syncthreads();
        // logits partial (from staged hi+lo)
        if (tid < 128) {
            int nn = tid >> 1, o = tid & 1;
            #pragma unroll 8
            for (int k = 0; k < 128; k++) {
                float xv = __bfloat162float(Xhi[nn * K4_PAD + k]) +
                           __bfloat162float(Xlo[nn * K4_PAD + k]);
                ls += xv * swa[2 * (kbase + k) + o];
            }
        }
        // MMA over this chunk
        #pragma unroll
        for (int ks = 0; ks < 8; ks++) {
            const unsigned koff = ks * 32;
            unsigned ah0, ah1, ah2, ah3, al0, al1, al2, al3;
            LDSM4(ah0, ah1, ah2, ah3, aAhi + koff);
            LDSM4(al0, al1, al2, al3, aAlo + koff);
            #pragma unroll
            for (int ns = 0; ns < 8; ns++) {
                int brow = wc + ns * 8 + brow_off;
                unsigned bh0, bh1, bl0, bl1;
                LDSM2(bh0, bh1, sm_u32(Whi + brow * K4_PAD + bk) + koff);
                LDSM2(bl0, bl1, sm_u32(Wlo + brow * K4_PAD + bk) + koff);
                MMA_BF16(C[ns][0], C[ns][1], C[ns][2], C[ns][3],
                         ah0, ah1, ah2, ah3, bh0, bh1);
                MMA_BF16(C[ns][0], C[ns][1], C[ns][2], C[ns][3],
                         ah0, ah1, ah2, ah3, bl0, bl1);
                MMA_BF16(C[ns][0], C[ns][1], C[ns][2], C[ns][3],
                         al0, al1, al2, al3, bh0, bh1);
            }
        }
    }
    #pragma unroll
    for (int ns = 0; ns < 8; ns++) {
        int col = wc + ns * 8 + 2 * tg;
        int r0 = n0 + wr + gq;
        if (r0 < n_nodes)
            *reinterpret_cast<float2*>(g_h2 + (size_t)r0 * OUT2 + col) =
                make_float2(C[ns][0], C[ns][1]);
        if (r0 + 8 < n_nodes)
            *reinterpret_cast<float2*>(g_h2 + (size_t)(r0 + 8) * OUT2 + col) =
                make_float2(C[ns][2], C[ns][3]);
    }
    if (tid < 128) {
        int nn = tid >> 1, o = tid & 1;
        int g = n0 + nn;
        if (g < n_nodes) {
            if (o == 0) g_as2[g] = ls;
            else        g_ad2[g] = ls;
        }
    }
}

// ============ KA2: gather aggregation, layer 2 ============
__global__ void ka2(int n_nodes, const float* __restrict__ b2,
                    float* __restrict__ out) {
    __shared__ int   ssrc[128];
    __shared__ float sw[128];
    const int d = blockIdx.x;
    const int j = threadIdx.x;   // 128
    float add = g_ad2[d];
    float w0 = lrelu_exp(g_as2[d] + add);
    float den = w0;
    float acc = w0 * g_h2[(size_t)d * OUT2 + j];
    const int pB = g_off[d], pE = g_off[d + 1];
    for (int p0 = pB; p0 < pE; p0 += 128) {
        int np = min(128, pE - p0);
        __syncthreads();
        if (j < np) {
            int s = g_csrc[p0 + j];
            ssrc[j] = s;
            sw[j] = lrelu_exp(g_as2[s] + add);
        }
        __syncthreads();
        #pragma unroll 4
        for (int e = 0; e < np; e++) {
            int s = ssrc[e];
            float wp = sw[e];
            den += wp;
            acc += wp * g_h2[(size_t)s * OUT2 + j];
        }
    }
    out[(size_t)d * OUT2 + j] = acc / den + b2[j];
}

extern "C" void kernel_launch(void* const* d_in, const int* in_sizes, int n_in,
                              void* d_out, int out_size) {
    const float* x    = (const float*)d_in[0];
    const void*  ei   = d_in[1];
    const float* W1   = (const float*)d_in[2];
    const float* as1  = (const float*)d_in[3];
    const float* ad1  = (const float*)d_in[4];
    const float* b1   = (const float*)d_in[5];
    const float* W2   = (const float*)d_in[6];
    const float* as2  = (const float*)d_in[7];
    const float* ad2  = (const float*)d_in[8];
    const float* b2   = (const float*)d_in[9];
    float* out = (float*)d_out;

    const int n_nodes = in_sizes[0] / NF;
    const int E  = in_sizes[1] / 2;

    const int eb = (E + 255) / 256;
    const int nb = (n_nodes + 1023) / 1024;

    static int smem_set = 0;
    if (!smem_set) {
        cudaFuncSetAttribute(k1_gemm1, cudaFuncAttributeMaxDynamicSharedMemorySize, K1_SMEM);
        cudaFuncSetAttribute(k4_gemm2, cudaFuncAttributeMaxDynamicSharedMemorySize, K4_SMEM);
        smem_set = 1;
    }

    dim3 g1((n_nodes + 63) / 64, HH / 64);
    const int g4 = (n_nodes + 63) / 64;

    kz<<<nb + 1, 1024>>>((const int*)ei, E, n_nodes);          // 1
    kc2_count<<<eb, 256>>>(ei, E);                             // 2
    kv<<<6, 256>>>(W1, as1, ad1, W2, as2, ad2);                // 3
    k1_gemm1<<<g1, 256, K1_SMEM>>>(x, W1, n_nodes);            // 4  <- profiled slot
    ks_alpha1<<<(n_nodes + 31) / 32, 256>>>(x, n_nodes);       // 5
    s1_scan<<<nb, 1024>>>(n_nodes);                            // 6
    s2_scan<<<1, 32>>>(nb);                                    // 7
    s3_scan<<<nb, 1024>>>(n_nodes, E);                         // 8
    kc3w1<<<eb, 256>>>(ei, E);                                 // 9
    ka1<<<n_nodes, 256>>>(n_nodes);                            // 10
    k4_gemm2<<<g4, 256, K4_SMEM>>>(W2, b1, n_nodes);           // 11
    ka2<<<n_nodes, 128>>>(n_nodes, b2, out);                   // 12
}

// round 11
// speedup vs baseline: 1.2504x; 1.2504x over previous
#include <cuda_runtime.h>
#include <cuda_bf16.h>

#define NMAX   50016
#define EMAX   800000
#define NF     128
#define HH     256
#define OUT2   128
#define NHEADS 4
#define NEG    0.2f

// ---- scratch ----
__device__ float g_h1  [(size_t)NMAX * HH];
__device__ float g_agg1[(size_t)NMAX * HH];
__device__ float g_h2  [(size_t)NMAX * OUT2];
__device__ float g_as1[NMAX * NHEADS];
__device__ float g_ad1[NMAX * NHEADS];
__device__ float g_as2[NMAX];
__device__ float g_ad2[NMAX];
__device__ float g_va1[NF * 8];
__device__ float g_wa2[HH * 2];
__device__ int   g_is64;
// CSR
__device__ int   g_cnt [NMAX + 1];
__device__ int   g_off [NMAX + 1];
__device__ int   g_cur [NMAX + 1];
__device__ int   g_bsum[64];
__device__ int   g_boff[64];
__device__ int   g_csrc[EMAX];
__device__ float g_w1  [(size_t)EMAX * NHEADS];

__device__ __forceinline__ void load_edge(const void* ei, int E, int i,
                                          int& s, int& d) {
    if (g_is64) {
        const long long* p = (const long long*)ei;
        s = (int)p[i]; d = (int)p[(size_t)E + i];
    } else {
        const int* p = (const int*)ei;
        s = p[i]; d = p[E + i];
    }
}

__device__ __forceinline__ float lrelu_exp(float v) {
    v = v > 0.f ? v : NEG * v;
    return __expf(v);
}

#define MMA_BF16(c0,c1,c2,c3,a0,a1,a2,a3,b0,b1) \
    asm("mma.sync.aligned.m16n8k16.row.col.f32.bf16.bf16.f32 " \
        "{%0,%1,%2,%3}, {%4,%5,%6,%7}, {%8,%9}, {%0,%1,%2,%3};" \
        : "+f"(c0), "+f"(c1), "+f"(c2), "+f"(c3) \
        : "r"(a0), "r"(a1), "r"(a2), "r"(a3), "r"(b0), "r"(b1))

#define LDSM4(R0,R1,R2,R3,A) \
    asm volatile("ldmatrix.sync.aligned.m8n8.x4.shared.b16 {%0,%1,%2,%3}, [%4];" \
        : "=r"(R0), "=r"(R1), "=r"(R2), "=r"(R3) : "r"(A))
#define LDSM2T(R0,R1,A) \
    asm volatile("ldmatrix.sync.aligned.m8n8.x2.trans.shared.b16 {%0,%1}, [%2];" \
        : "=r"(R0), "=r"(R1) : "r"(A))

__device__ __forceinline__ unsigned sm_u32(const void* p) {
    return (unsigned)__cvta_generic_to_shared(p);
}

__device__ __forceinline__ unsigned bf16_hi_pack(float a, float b) {
    unsigned ua = (unsigned)__bfloat16_as_ushort(__float2bfloat16(a));
    unsigned ub = (unsigned)__bfloat16_as_ushort(__float2bfloat16(b));
    return ua | (ub << 16);
}
__device__ __forceinline__ unsigned bf16_lo_pack(float a, float b) {
    float ra = a - __bfloat162float(__float2bfloat16(a));
    float rb = b - __bfloat162float(__float2bfloat16(b));
    return bf16_hi_pack(ra, rb);
}

// ============ KZ: dtype probe + zero counts ============
__global__ void kz(const int* ei32, int E, int n) {
    int i = blockIdx.x * 1024 + threadIdx.x;
    if (i <= n) g_cnt[i] = 0;
    if (blockIdx.x == 0) {
        __shared__ int flag;
        if (threadIdx.x == 0) flag = 0;
        __syncthreads();
        for (int j = threadIdx.x; j < 2048; j += 1024) {
            int idx = 2 * j + 1;
            if (idx < 2 * E && ei32[idx] != 0) flag = 1;
        }
        __syncthreads();
        if (threadIdx.x == 0) g_is64 = (flag == 0);
    }
}

// ============ KC2: count in-degrees ============
__global__ void kc2_count(const void* __restrict__ ei, int E) {
    int i = blockIdx.x * blockDim.x + threadIdx.x;
    if (i >= E) return;
    int s, d; load_edge(ei, E, i, s, d);
    atomicAdd(&g_cnt[d], 1);
}

// ============ KV: attention-vector precomputes ============
__global__ void kv(const float* __restrict__ W1, const float* __restrict__ a_s1,
                   const float* __restrict__ a_d1, const float* __restrict__ W2,
                   const float* __restrict__ a_s2, const float* __restrict__ a_d2) {
    int t = blockIdx.x * 256 + threadIdx.x;
    if (t < NF * 8) {
        int k = t >> 3, o = t & 7, h = o & 3;
        const float* a = (o < 4 ? a_s1 : a_d1) + h * 64;
        const float* w = W1 + (size_t)k * HH + h * 64;
        float s = 0.f;
        #pragma unroll 8
        for (int c = 0; c < 64; c++) s += w[c] * a[c];
        g_va1[t] = s;
    } else if (t < NF * 8 + HH * 2) {
        int q = t - NF * 8;
        int k = q >> 1, o = q & 1;
        const float* a = o ? a_d2 : a_s2;
        const float* w = W2 + (size_t)k * OUT2;
        float s = 0.f;
        #pragma unroll 8
        for (int c = 0; c < OUT2; c++) s += w[c] * a[c];
        g_wa2[q] = s;
    }
}

// ============ K1: h1 = x @ W1  (bf16-split MMA, 32x32 warp tiles) ============
// 128 threads = 4 warps (2 row x 2 col), block tile 64x64.
#define K1_XPAD  136
#define K1_WPAD  72
#define K1_XSZ   (64 * K1_XPAD)
#define K1_WSZ   (128 * K1_WPAD)
#define K1_SMEM  ((2 * K1_XSZ + 2 * K1_WSZ) * 2)
__global__ void k1_gemm1(const float* __restrict__ x, const float* __restrict__ W1,
                         int n_nodes) {
    extern __shared__ __nv_bfloat16 smb[];
    __nv_bfloat16* Xhi = smb;
    __nv_bfloat16* Xlo = smb + K1_XSZ;
    __nv_bfloat16* Whi = smb + 2 * K1_XSZ;             // k-major [k][col]
    __nv_bfloat16* Wlo = smb + 2 * K1_XSZ + K1_WSZ;
    const int n0 = blockIdx.x * 64;
    const int c0 = blockIdx.y * 64;
    const int tid = threadIdx.x;                        // 128

    // stage X tile (64 rows x 128 k), row-major, hi/lo split
    #pragma unroll
    for (int r = 0; r < 16; r++) {
        int i = tid + r * 128;
        int nn = i >> 5, k4 = i & 31;
        int g = n0 + nn;
        float4 v = make_float4(0.f, 0.f, 0.f, 0.f);
        if (g < n_nodes) v = *reinterpret_cast<const float4*>(x + (size_t)g * NF + 4 * k4);
        uint2 hp, lp;
        hp.x = bf16_hi_pack(v.x, v.y); hp.y = bf16_hi_pack(v.z, v.w);
        lp.x = bf16_lo_pack(v.x, v.y); lp.y = bf16_lo_pack(v.z, v.w);
        *reinterpret_cast<uint2*>(&Xhi[nn * K1_XPAD + 4 * k4]) = hp;
        *reinterpret_cast<uint2*>(&Xlo[nn * K1_XPAD + 4 * k4]) = lp;
    }
    // stage W slab (128 k x 64 cols), k-major (coalesced, conflict-free)
    #pragma unroll
    for (int r = 0; r < 16; r++) {
        int i = tid + r * 128;
        int k = i >> 4, c4 = i & 15;
        float4 w = *reinterpret_cast<const float4*>(W1 + (size_t)k * HH + c0 + 4 * c4);
        uint2 hp, lp;
        hp.x = bf16_hi_pack(w.x, w.y); hp.y = bf16_hi_pack(w.z, w.w);
        lp.x = bf16_lo_pack(w.x, w.y); lp.y = bf16_lo_pack(w.z, w.w);
        *reinterpret_cast<uint2*>(&Whi[k * K1_WPAD + 4 * c4]) = hp;
        *reinterpret_cast<uint2*>(&Wlo[k * K1_WPAD + 4 * c4]) = lp;
    }
    __syncthreads();

    const int wid = tid >> 5, lane = tid & 31;
    const int wr = (wid & 1) * 32;
    const int wc = (wid >> 1) * 32;
    const int gq = lane >> 2, tg = lane & 3;

    unsigned aAhi[2], aAlo[2];
    {
        const int ak = (lane >> 4) * 8;
        #pragma unroll
        for (int rg = 0; rg < 2; rg++) {
            int row = wr + rg * 16 + (lane & 15);
            aAhi[rg] = sm_u32(Xhi + row * K1_XPAD + ak);
            aAlo[rg] = sm_u32(Xlo + row * K1_XPAD + ak);
        }
    }
    unsigned aBhi = sm_u32(Whi + (lane & 15) * K1_WPAD + wc);
    unsigned aBlo = sm_u32(Wlo + (lane & 15) * K1_WPAD + wc);

    float C[2][4][4] = {};
    #pragma unroll
    for (int ks = 0; ks < 8; ks++) {
        const unsigned koffA = ks * 32;                 // 16 bf16 = 32 B
        const unsigned koffB = ks * 16 * K1_WPAD * 2;   // 16 k-rows
        unsigned ah[2][4], al[2][4];
        #pragma unroll
        for (int rg = 0; rg < 2; rg++) {
            LDSM4(ah[rg][0], ah[rg][1], ah[rg][2], ah[rg][3], aAhi[rg] + koffA);
            LDSM4(al[rg][0], al[rg][1], al[rg][2], al[rg][3], aAlo[rg] + koffA);
        }
        #pragma unroll
        for (int ns = 0; ns < 4; ns++) {
            unsigned bh0, bh1, bl0, bl1;
            LDSM2T(bh0, bh1, aBhi + koffB + ns * 16);
            LDSM2T(bl0, bl1, aBlo + koffB + ns * 16);
            #pragma unroll
            for (int rg = 0; rg < 2; rg++) {
                MMA_BF16(C[rg][ns][0], C[rg][ns][1], C[rg][ns][2], C[rg][ns][3],
                         ah[rg][0], ah[rg][1], ah[rg][2], ah[rg][3], bh0, bh1);
                MMA_BF16(C[rg][ns][0], C[rg][ns][1], C[rg][ns][2], C[rg][ns][3],
                         ah[rg][0], ah[rg][1], ah[rg][2], ah[rg][3], bl0, bl1);
                MMA_BF16(C[rg][ns][0], C[rg][ns][1], C[rg][ns][2], C[rg][ns][3],
                         al[rg][0], al[rg][1], al[rg][2], al[rg][3], bh0, bh1);
            }
        }
    }
    #pragma unroll
    for (int rg = 0; rg < 2; rg++) {
        #pragma unroll
        for (int ns = 0; ns < 4; ns++) {
            int col = c0 + wc + ns * 8 + 2 * tg;
            int r0 = n0 + wr + rg * 16 + gq;
            if (r0 < n_nodes)
                *reinterpret_cast<float2*>(g_h1 + (size_t)r0 * HH + col) =
                    make_float2(C[rg][ns][0], C[rg][ns][1]);
            if (r0 + 8 < n_nodes)
                *reinterpret_cast<float2*>(g_h1 + (size_t)(r0 + 8) * HH + col) =
                    make_float2(C[rg][ns][2], C[rg][ns][3]);
        }
    }
}

// ============ KS1: layer-1 logits ============
__global__ void ks_alpha1(const float* __restrict__ x, int n_nodes) {
    __shared__ float xv[32][NF];
    __shared__ float sva[NF * 8];
    const int n0 = blockIdx.x * 32;
    const int tid = threadIdx.x;      // 256
    for (int i = tid; i < NF * 8; i += 256) sva[i] = g_va1[i];
    #pragma unroll
    for (int r = 0; r < 4; r++) {
        int i = tid + r * 256;
        int nn = i >> 5, k4 = i & 31;
        int g = n0 + nn;
        float4 v = make_float4(0.f, 0.f, 0.f, 0.f);
        if (g < n_nodes) v = *reinterpret_cast<const float4*>(x + (size_t)g * NF + 4 * k4);
        *reinterpret_cast<float4*>(&xv[nn][4 * k4]) = v;
    }
    __syncthreads();
    int nn = tid >> 3, o = tid & 7;
    int g = n0 + nn;
    float s = 0.f;
    #pragma unroll 8
    for (int k = 0; k < NF; k++) s += xv[nn][k] * sva[k * 8 + o];
    if (g < n_nodes) {
        if (o < 4) g_as1[g * 4 + o] = s;
        else       g_ad1[g * 4 + o - 4] = s;
    }
}

// ============ scan ============
__global__ void s1_scan(int n) {
    __shared__ int sd[1024];
    int tid = threadIdx.x;
    int i = blockIdx.x * 1024 + tid;
    int v = (i < n) ? g_cnt[i] : 0;
    sd[tid] = v;
    __syncthreads();
    #pragma unroll
    for (int off = 1; off < 1024; off <<= 1) {
        int t = (tid >= off) ? sd[tid - off] : 0;
        __syncthreads();
        sd[tid] += t;
        __syncthreads();
    }
    if (i < n) g_off[i] = sd[tid] - v;
    if (tid == 1023) g_bsum[blockIdx.x] = sd[1023];
}
__global__ void s2_scan(int nb) {
    if (threadIdx.x == 0) {
        int acc = 0;
        for (int b = 0; b < nb; b++) { int t = g_bsum[b]; g_boff[b] = acc; acc += t; }
    }
}
__global__ void s3_scan(int n, int E) {
    int i = blockIdx.x * 1024 + threadIdx.x;
    if (i < n) {
        int v = g_off[i] + g_boff[blockIdx.x];
        g_off[i] = v;
        g_cur[i] = v;
    }
    if (i == 0) g_off[n] = E;
}

// ============ KC3W1: CSR fill + layer-1 softmax numerators ============
__global__ void kc3w1(const void* __restrict__ ei, int E) {
    int i = blockIdx.x * blockDim.x + threadIdx.x;
    if (i >= E) return;
    int s, d; load_edge(ei, E, i, s, d);
    int p = atomicAdd(&g_cur[d], 1);
    g_csrc[p] = s;
    float4 as = *reinterpret_cast<const float4*>(g_as1 + 4 * s);
    float4 ad = *reinterpret_cast<const float4*>(g_ad1 + 4 * d);
    float4 w;
    w.x = lrelu_exp(as.x + ad.x);
    w.y = lrelu_exp(as.y + ad.y);
    w.z = lrelu_exp(as.z + ad.z);
    w.w = lrelu_exp(as.w + ad.w);
    *reinterpret_cast<float4*>(g_w1 + (size_t)p * 4) = w;
}

// ============ KA1: gather aggregation, layer 1 ============
__global__ void ka1(int n_nodes) {
    __shared__ int   ssrc[128];
    __shared__ float sw[128 * 4];
    const int d = blockIdx.x;
    const int j = threadIdx.x;    // 256
    const int h = j >> 6;
    float w0 = lrelu_exp(g_as1[d * NHEADS + h] + g_ad1[d * NHEADS + h]);
    float den = w0;
    float acc = w0 * g_h1[(size_t)d * HH + j];
    const int pB = g_off[d], pE = g_off[d + 1];
    for (int p0 = pB; p0 < pE; p0 += 128) {
        int np = min(128, pE - p0);
        __syncthreads();
        if (j < np) {
            ssrc[j] = g_csrc[p0 + j];
        } else if (j >= 128 && j - 128 < np) {
            int e = j - 128;
            *reinterpret_cast<float4*>(&sw[4 * e]) =
                *reinterpret_cast<const float4*>(g_w1 + (size_t)(p0 + e) * 4);
        }
        __syncthreads();
        #pragma unroll 4
        for (int e = 0; e < np; e++) {
            int s = ssrc[e];
            float wp = sw[4 * e + h];
            den += wp;
            acc += wp * g_h1[(size_t)s * HH + j];
        }
    }
    g_agg1[(size_t)d * HH + j] = acc / den;
}

// ============ K4: h2 = elu(agg1+b1) @ W2 (same MMA template, 2 k-chunks) ====
#define K4_XPAD  136
#define K4_WPAD  72
#define K4_XSZ   (64 * K4_XPAD)
#define K4_WSZ   (128 * K4_WPAD)
#define K4_SMEM  ((2 * K4_XSZ + 2 * K4_WSZ) * 2 + HH * 2 * 4)
__global__ void k4_gemm2(const float* __restrict__ W2, const float* __restrict__ b1,
                         int n_nodes) {
    extern __shared__ __nv_bfloat16 smb[];
    __nv_bfloat16* Xhi = smb;
    __nv_bfloat16* Xlo = smb + K4_XSZ;
    __nv_bfloat16* Whi = smb + 2 * K4_XSZ;
    __nv_bfloat16* Wlo = smb + 2 * K4_XSZ + K4_WSZ;
    float* swa = reinterpret_cast<float*>(smb + 2 * K4_XSZ + 2 * K4_WSZ);
    const int n0 = blockIdx.x * 64;
    const int c0 = blockIdx.y * 64;
    const int tid = threadIdx.x;      // 128
    const bool do_logits = (blockIdx.y == 0);
    if (do_logits) for (int i = tid; i < HH * 2; i += 128) swa[i] = g_wa2[i];

    const int wid = tid >> 5, lane = tid & 31;
    const int wr = (wid & 1) * 32;
    const int wc = (wid >> 1) * 32;
    const int gq = lane >> 2, tg = lane & 3;

    unsigned aAhi[2], aAlo[2];
    {
        const int ak = (lane >> 4) * 8;
        #pragma unroll
        for (int rg = 0; rg < 2; rg++) {
            int row = wr + rg * 16 + (lane & 15);
            aAhi[rg] = sm_u32(Xhi + row * K4_XPAD + ak);
            aAlo[rg] = sm_u32(Xlo + row * K4_XPAD + ak);
        }
    }
    unsigned aBhi = sm_u32(Whi + (lane & 15) * K4_WPAD + wc);
    unsigned aBlo = sm_u32(Wlo + (lane & 15) * K4_WPAD + wc);

    float C[2][4][4] = {};
    float ls = 0.f;
    #pragma unroll
    for (int kc = 0; kc < 2; kc++) {
        const int kbase = kc * 128;
        __syncthreads();
        // stage X chunk: elu(agg1+b1), hi/lo split
        #pragma unroll
        for (int r = 0; r < 16; r++) {
            int i = tid + r * 128;
            int nn = i >> 5, k4 = i & 31;
            int g = n0 + nn;
            float4 v = make_float4(0.f, 0.f, 0.f, 0.f);
            if (g < n_nodes) {
                int kk = kbase + 4 * k4;
                v = *reinterpret_cast<const float4*>(g_agg1 + (size_t)g * HH + kk);
                float4 b = *reinterpret_cast<const float4*>(b1 + kk);
                v.x += b.x; v.y += b.y; v.z += b.z; v.w += b.w;
                v.x = v.x > 0.f ? v.x : expm1f(v.x);
                v.y = v.y > 0.f ? v.y : expm1f(v.y);
                v.z = v.z > 0.f ? v.z : expm1f(v.z);
                v.w = v.w > 0.f ? v.w : expm1f(v.w);
            }
            uint2 hp, lp;
            hp.x = bf16_hi_pack(v.x, v.y); hp.y = bf16_hi_pack(v.z, v.w);
            lp.x = bf16_lo_pack(v.x, v.y); lp.y = bf16_lo_pack(v.z, v.w);
            *reinterpret_cast<uint2*>(&Xhi[nn * K4_XPAD + 4 * k4]) = hp;
            *reinterpret_cast<uint2*>(&Xlo[nn * K4_XPAD + 4 * k4]) = lp;
        }
        // stage W chunk k-major (coalesced)
        #pragma unroll
        for (int r = 0; r < 16; r++) {
            int i = tid + r * 128;
            int k = i >> 4, c4 = i & 15;
            float4 w = *reinterpret_cast<const float4*>(
                W2 + (size_t)(kbase + k) * OUT2 + c0 + 4 * c4);
            uint2 hp, lp;
            hp.x = bf16_hi_pack(w.x, w.y); hp.y = bf16_hi_pack(w.z, w.w);
            lp.x = bf16_lo_pack(w.x, w.y); lp.y = bf16_lo_pack(w.z, w.w);
            *reinterpret_cast<uint2*>(&Whi[k * K4_WPAD + 4 * c4]) = hp;
            *reinterpret_cast<uint2*>(&Wlo[k * K4_WPAD + 4 * c4]) = lp;
        }
        __syncthreads();
        // logits partial from staged hi+lo (only col-block 0)
        if (do_logits) {
            int nn = tid >> 1, o = tid & 1;
            #pragma unroll 8
            for (int k = 0; k < 128; k++) {
                float xvv = __bfloat162float(Xhi[nn * K4_XPAD + k]) +
                            __bfloat162float(Xlo[nn * K4_XPAD + k]);
                ls += xvv * swa[2 * (kbase + k) + o];
            }
        }
        // MMA over this chunk
        #pragma unroll
        for (int ks = 0; ks < 8; ks++) {
            const unsigned koffA = ks * 32;
            const unsigned koffB = ks * 16 * K4_WPAD * 2;
            unsigned ah[2][4], al[2][4];
            #pragma unroll
            for (int rg = 0; rg < 2; rg++) {
                LDSM4(ah[rg][0], ah[rg][1], ah[rg][2], ah[rg][3], aAhi[rg] + koffA);
                LDSM4(al[rg][0], al[rg][1], al[rg][2], al[rg][3], aAlo[rg] + koffA);
            }
            #pragma unroll
            for (int ns = 0; ns < 4; ns++) {
                unsigned bh0, bh1, bl0, bl1;
                LDSM2T(bh0, bh1, aBhi + koffB + ns * 16);
                LDSM2T(bl0, bl1, aBlo + koffB + ns * 16);
                #pragma unroll
                for (int rg = 0; rg < 2; rg++) {
                    MMA_BF16(C[rg][ns][0], C[rg][ns][1], C[rg][ns][2], C[rg][ns][3],
                             ah[rg][0], ah[rg][1], ah[rg][2], ah[rg][3], bh0, bh1);
                    MMA_BF16(C[rg][ns][0], C[rg][ns][1], C[rg][ns][2], C[rg][ns][3],
                             ah[rg][0], ah[rg][1], ah[rg][2], ah[rg][3], bl0, bl1);
                    MMA_BF16(C[rg][ns][0], C[rg][ns][1], C[rg][ns][2], C[rg][ns][3],
                             al[rg][0], al[rg][1], al[rg][2], al[rg][3], bh0, bh1);
                }
            }
        }
    }
    #pragma unroll
    for (int rg = 0; rg < 2; rg++) {
        #pragma unroll
        for (int ns = 0; ns < 4; ns++) {
            int col = c0 + wc + ns * 8 + 2 * tg;
            int r0 = n0 + wr + rg * 16 + gq;
            if (r0 < n_nodes)
                *reinterpret_cast<float2*>(g_h2 + (size_t)r0 * OUT2 + col) =
                    make_float2(C[rg][ns][0], C[rg][ns][1]);
            if (r0 + 8 < n_nodes)
                *reinterpret_cast<float2*>(g_h2 + (size_t)(r0 + 8) * OUT2 + col) =
                    make_float2(C[rg][ns][2], C[rg][ns][3]);
        }
    }
    if (do_logits) {
        int nn = tid >> 1, o = tid & 1;
        int g = n0 + nn;
        if (g < n_nodes) {
            if (o == 0) g_as2[g] = ls;
            else        g_ad2[g] = ls;
        }
    }
}

// ============ KA2: gather aggregation, layer 2 ============
__global__ void ka2(int n_nodes, const float* __restrict__ b2,
                    float* __restrict__ out) {
    __shared__ int   ssrc[128];
    __shared__ float sw[128];
    const int d = blockIdx.x;
    const int j = threadIdx.x;   // 128
    float add = g_ad2[d];
    float w0 = lrelu_exp(g_as2[d] + add);
    float den = w0;
    float acc = w0 * g_h2[(size_t)d * OUT2 + j];
    const int pB = g_off[d], pE = g_off[d + 1];
    for (int p0 = pB; p0 < pE; p0 += 128) {
        int np = min(128, pE - p0);
        __syncthreads();
        if (j < np) {
            int s = g_csrc[p0 + j];
            ssrc[j] = s;
            sw[j] = lrelu_exp(g_as2[s] + add);
        }
        __syncthreads();
        #pragma unroll 4
        for (int e = 0; e < np; e++) {
            int s = ssrc[e];
            float wp = sw[e];
            den += wp;
            acc += wp * g_h2[(size_t)s * OUT2 + j];
        }
    }
    out[(size_t)d * OUT2 + j] = acc / den + b2[j];
}

extern "C" void kernel_launch(void* const* d_in, const int* in_sizes, int n_in,
                              void* d_out, int out_size) {
    const float* x    = (const float*)d_in[0];
    const void*  ei   = d_in[1];
    const float* W1   = (const float*)d_in[2];
    const float* as1  = (const float*)d_in[3];
    const float* ad1  = (const float*)d_in[4];
    const float* b1   = (const float*)d_in[5];
    const float* W2   = (const float*)d_in[6];
    const float* as2  = (const float*)d_in[7];
    const float* ad2  = (const float*)d_in[8];
    const float* b2   = (const float*)d_in[9];
    float* out = (float*)d_out;

    const int n_nodes = in_sizes[0] / NF;
    const int E  = in_sizes[1] / 2;

    const int eb = (E + 255) / 256;
    const int nb = (n_nodes + 1023) / 1024;

    static int smem_set = 0;
    if (!smem_set) {
        cudaFuncSetAttribute(k1_gemm1, cudaFuncAttributeMaxDynamicSharedMemorySize, K1_SMEM);
        cudaFuncSetAttribute(k4_gemm2, cudaFuncAttributeMaxDynamicSharedMemorySize, K4_SMEM);
        smem_set = 1;
    }

    dim3 g1((n_nodes + 63) / 64, HH / 64);      // 782 x 4
    dim3 g4((n_nodes + 63) / 64, OUT2 / 64);    // 782 x 2

    kz<<<nb + 1, 1024>>>((const int*)ei, E, n_nodes);          // 1
    kc2_count<<<eb, 256>>>(ei, E);                             // 2
    kv<<<6, 256>>>(W1, as1, ad1, W2, as2, ad2);                // 3
    k1_gemm1<<<g1, 128, K1_SMEM>>>(x, W1, n_nodes);            // 4  <- profiled slot
    ks_alpha1<<<(n_nodes + 31) / 32, 256>>>(x, n_nodes);       // 5
    s1_scan<<<nb, 1024>>>(n_nodes);                            // 6
    s2_scan<<<1, 32>>>(nb);                                    // 7
    s3_scan<<<nb, 1024>>>(n_nodes, E);                         // 8
    kc3w1<<<eb, 256>>>(ei, E);                                 // 9
    ka1<<<n_nodes, 256>>>(n_nodes);                            // 10
    k4_gemm2<<<g4, 128, K4_SMEM>>>(W2, b1, n_nodes);           // 11
    ka2<<<n_nodes, 128>>>(n_nodes, b2, out);                   // 12
}

// round 12
// speedup vs baseline: 1.6632x; 1.3301x over previous
#include <cuda_runtime.h>
#include <cuda_bf16.h>
#include <cuda_fp16.h>

#define NMAX   50016
#define EMAX   800000
#define NF     128
#define HH     256
#define OUT2   128
#define NHEADS 4
#define NEG    0.2f

// ---- scratch ----
__device__ __half g_h1[(size_t)NMAX * HH];     // fp16 layer-1 features
__device__ float  g_agg1[(size_t)NMAX * HH];
__device__ __half g_h2[(size_t)NMAX * OUT2];   // fp16 layer-2 features
__device__ float g_as1[NMAX * NHEADS];
__device__ float g_ad1[NMAX * NHEADS];
__device__ float g_as2[NMAX];
__device__ float g_ad2[NMAX];
__device__ float g_va1[NF * 8];
__device__ float g_wa2[HH * 2];
__device__ int   g_is64;
// CSR
__device__ int   g_cnt [NMAX + 1];
__device__ int   g_off [NMAX + 1];
__device__ int   g_cur [NMAX + 1];
__device__ int   g_bsum[64];
__device__ int   g_boff[64];
__device__ int   g_csrc[EMAX];
__device__ float g_w1  [(size_t)EMAX * NHEADS];

__device__ __forceinline__ void load_edge(const void* ei, int E, int i,
                                          int& s, int& d) {
    if (g_is64) {
        const long long* p = (const long long*)ei;
        s = (int)p[i]; d = (int)p[(size_t)E + i];
    } else {
        const int* p = (const int*)ei;
        s = p[i]; d = p[E + i];
    }
}

__device__ __forceinline__ float lrelu_exp(float v) {
    v = v > 0.f ? v : NEG * v;
    return __expf(v);
}

#define MMA_BF16(c0,c1,c2,c3,a0,a1,a2,a3,b0,b1) \
    asm("mma.sync.aligned.m16n8k16.row.col.f32.bf16.bf16.f32 " \
        "{%0,%1,%2,%3}, {%4,%5,%6,%7}, {%8,%9}, {%0,%1,%2,%3};" \
        : "+f"(c0), "+f"(c1), "+f"(c2), "+f"(c3) \
        : "r"(a0), "r"(a1), "r"(a2), "r"(a3), "r"(b0), "r"(b1))

#define LDSM4(R0,R1,R2,R3,A) \
    asm volatile("ldmatrix.sync.aligned.m8n8.x4.shared.b16 {%0,%1,%2,%3}, [%4];" \
        : "=r"(R0), "=r"(R1), "=r"(R2), "=r"(R3) : "r"(A))
#define LDSM2T(R0,R1,A) \
    asm volatile("ldmatrix.sync.aligned.m8n8.x2.trans.shared.b16 {%0,%1}, [%2];" \
        : "=r"(R0), "=r"(R1) : "r"(A))

__device__ __forceinline__ unsigned sm_u32(const void* p) {
    return (unsigned)__cvta_generic_to_shared(p);
}

__device__ __forceinline__ unsigned bf16_hi_pack(float a, float b) {
    unsigned ua = (unsigned)__bfloat16_as_ushort(__float2bfloat16(a));
    unsigned ub = (unsigned)__bfloat16_as_ushort(__float2bfloat16(b));
    return ua | (ub << 16);
}
__device__ __forceinline__ unsigned bf16_lo_pack(float a, float b) {
    float ra = a - __bfloat162float(__float2bfloat16(a));
    float rb = b - __bfloat162float(__float2bfloat16(b));
    return bf16_hi_pack(ra, rb);
}

// ============ KZ: dtype probe + zero counts ============
__global__ void kz(const int* ei32, int E, int n) {
    int i = blockIdx.x * 1024 + threadIdx.x;
    if (i <= n) g_cnt[i] = 0;
    if (blockIdx.x == 0) {
        __shared__ int flag;
        if (threadIdx.x == 0) flag = 0;
        __syncthreads();
        for (int j = threadIdx.x; j < 2048; j += 1024) {
            int idx = 2 * j + 1;
            if (idx < 2 * E && ei32[idx] != 0) flag = 1;
        }
        __syncthreads();
        if (threadIdx.x == 0) g_is64 = (flag == 0);
    }
}

// ============ KC2: count in-degrees ============
__global__ void kc2_count(const void* __restrict__ ei, int E) {
    int i = blockIdx.x * blockDim.x + threadIdx.x;
    if (i >= E) return;
    int s, d; load_edge(ei, E, i, s, d);
    atomicAdd(&g_cnt[d], 1);
}

// ============ KV: attention-vector precomputes ============
__global__ void kv(const float* __restrict__ W1, const float* __restrict__ a_s1,
                   const float* __restrict__ a_d1, const float* __restrict__ W2,
                   const float* __restrict__ a_s2, const float* __restrict__ a_d2) {
    int t = blockIdx.x * 256 + threadIdx.x;
    if (t < NF * 8) {
        int k = t >> 3, o = t & 7, h = o & 3;
        const float* a = (o < 4 ? a_s1 : a_d1) + h * 64;
        const float* w = W1 + (size_t)k * HH + h * 64;
        float s = 0.f;
        #pragma unroll 8
        for (int c = 0; c < 64; c++) s += w[c] * a[c];
        g_va1[t] = s;
    } else if (t < NF * 8 + HH * 2) {
        int q = t - NF * 8;
        int k = q >> 1, o = q & 1;
        const float* a = o ? a_d2 : a_s2;
        const float* w = W2 + (size_t)k * OUT2;
        float s = 0.f;
        #pragma unroll 8
        for (int c = 0; c < OUT2; c++) s += w[c] * a[c];
        g_wa2[q] = s;
    }
}

// ============ K1: h1 = x @ W1  (bf16-split MMA) + fused layer-1 logits ======
#define K1_XPAD  136
#define K1_WPAD  72
#define K1_XSZ   (64 * K1_XPAD)
#define K1_WSZ   (128 * K1_WPAD)
#define K1_SMEM  ((2 * K1_XSZ + 2 * K1_WSZ) * 2 + NF * 8 * 4)
__global__ void k1_gemm1(const float* __restrict__ x, const float* __restrict__ W1,
                         int n_nodes) {
    extern __shared__ __nv_bfloat16 smb[];
    __nv_bfloat16* Xhi = smb;
    __nv_bfloat16* Xlo = smb + K1_XSZ;
    __nv_bfloat16* Whi = smb + 2 * K1_XSZ;
    __nv_bfloat16* Wlo = smb + 2 * K1_XSZ + K1_WSZ;
    float* sva = reinterpret_cast<float*>(smb + 2 * K1_XSZ + 2 * K1_WSZ);
    const int n0 = blockIdx.x * 64;
    const int c0 = blockIdx.y * 64;
    const int tid = threadIdx.x;                        // 128
    const bool do_logits = (blockIdx.y == 0);
    if (do_logits) for (int i = tid; i < NF * 8; i += 128) sva[i] = g_va1[i];

    #pragma unroll
    for (int r = 0; r < 16; r++) {
        int i = tid + r * 128;
        int nn = i >> 5, k4 = i & 31;
        int g = n0 + nn;
        float4 v = make_float4(0.f, 0.f, 0.f, 0.f);
        if (g < n_nodes) v = *reinterpret_cast<const float4*>(x + (size_t)g * NF + 4 * k4);
        uint2 hp, lp;
        hp.x = bf16_hi_pack(v.x, v.y); hp.y = bf16_hi_pack(v.z, v.w);
        lp.x = bf16_lo_pack(v.x, v.y); lp.y = bf16_lo_pack(v.z, v.w);
        *reinterpret_cast<uint2*>(&Xhi[nn * K1_XPAD + 4 * k4]) = hp;
        *reinterpret_cast<uint2*>(&Xlo[nn * K1_XPAD + 4 * k4]) = lp;
    }
    #pragma unroll
    for (int r = 0; r < 16; r++) {
        int i = tid + r * 128;
        int k = i >> 4, c4 = i & 15;
        float4 w = *reinterpret_cast<const float4*>(W1 + (size_t)k * HH + c0 + 4 * c4);
        uint2 hp, lp;
        hp.x = bf16_hi_pack(w.x, w.y); hp.y = bf16_hi_pack(w.z, w.w);
        lp.x = bf16_lo_pack(w.x, w.y); lp.y = bf16_lo_pack(w.z, w.w);
        *reinterpret_cast<uint2*>(&Whi[k * K1_WPAD + 4 * c4]) = hp;
        *reinterpret_cast<uint2*>(&Wlo[k * K1_WPAD + 4 * c4]) = lp;
    }
    __syncthreads();

    const int wid = tid >> 5, lane = tid & 31;
    const int wr = (wid & 1) * 32;
    const int wc = (wid >> 1) * 32;
    const int gq = lane >> 2, tg = lane & 3;

    unsigned aAhi[2], aAlo[2];
    {
        const int ak = (lane >> 4) * 8;
        #pragma unroll
        for (int rg = 0; rg < 2; rg++) {
            int row = wr + rg * 16 + (lane & 15);
            aAhi[rg] = sm_u32(Xhi + row * K1_XPAD + ak);
            aAlo[rg] = sm_u32(Xlo + row * K1_XPAD + ak);
        }
    }
    unsigned aBhi = sm_u32(Whi + (lane & 15) * K1_WPAD + wc);
    unsigned aBlo = sm_u32(Wlo + (lane & 15) * K1_WPAD + wc);

    float C[2][4][4] = {};
    #pragma unroll
    for (int ks = 0; ks < 8; ks++) {
        const unsigned koffA = ks * 32;
        const unsigned koffB = ks * 16 * K1_WPAD * 2;
        unsigned ah[2][4], al[2][4];
        #pragma unroll
        for (int rg = 0; rg < 2; rg++) {
            LDSM4(ah[rg][0], ah[rg][1], ah[rg][2], ah[rg][3], aAhi[rg] + koffA);
            LDSM4(al[rg][0], al[rg][1], al[rg][2], al[rg][3], aAlo[rg] + koffA);
        }
        #pragma unroll
        for (int ns = 0; ns < 4; ns++) {
            unsigned bh0, bh1, bl0, bl1;
            LDSM2T(bh0, bh1, aBhi + koffB + ns * 16);
            LDSM2T(bl0, bl1, aBlo + koffB + ns * 16);
            #pragma unroll
            for (int rg = 0; rg < 2; rg++) {
                MMA_BF16(C[rg][ns][0], C[rg][ns][1], C[rg][ns][2], C[rg][ns][3],
                         ah[rg][0], ah[rg][1], ah[rg][2], ah[rg][3], bh0, bh1);
                MMA_BF16(C[rg][ns][0], C[rg][ns][1], C[rg][ns][2], C[rg][ns][3],
                         ah[rg][0], ah[rg][1], ah[rg][2], ah[rg][3], bl0, bl1);
                MMA_BF16(C[rg][ns][0], C[rg][ns][1], C[rg][ns][2], C[rg][ns][3],
                         al[rg][0], al[rg][1], al[rg][2], al[rg][3], bh0, bh1);
            }
        }
    }
    #pragma unroll
    for (int rg = 0; rg < 2; rg++) {
        #pragma unroll
        for (int ns = 0; ns < 4; ns++) {
            int col = c0 + wc + ns * 8 + 2 * tg;
            int r0 = n0 + wr + rg * 16 + gq;
            if (r0 < n_nodes)
                *reinterpret_cast<__half2*>(g_h1 + (size_t)r0 * HH + col) =
                    __floats2half2_rn(C[rg][ns][0], C[rg][ns][1]);
            if (r0 + 8 < n_nodes)
                *reinterpret_cast<__half2*>(g_h1 + (size_t)(r0 + 8) * HH + col) =
                    __floats2half2_rn(C[rg][ns][2], C[rg][ns][3]);
        }
    }
    // fused layer-1 logits: 128 thr = 64 nodes x 2 quads (as1 / ad1)
    if (do_logits) {
        int nn = tid >> 1, o4 = (tid & 1) * 4;
        float s0 = 0.f, s1 = 0.f, s2 = 0.f, s3 = 0.f;
        #pragma unroll 8
        for (int k = 0; k < NF; k++) {
            float xv = __bfloat162float(Xhi[nn * K1_XPAD + k]) +
                       __bfloat162float(Xlo[nn * K1_XPAD + k]);
            const float* sv = sva + k * 8 + o4;
            s0 += xv * sv[0]; s1 += xv * sv[1];
            s2 += xv * sv[2]; s3 += xv * sv[3];
        }
        int g = n0 + nn;
        if (g < n_nodes) {
            float* dst = (o4 == 0 ? g_as1 : g_ad1) + g * 4;
            *reinterpret_cast<float4*>(dst) = make_float4(s0, s1, s2, s3);
        }
    }
}

// ============ scan ============
__global__ void s1_scan(int n) {
    __shared__ int sd[1024];
    int tid = threadIdx.x;
    int i = blockIdx.x * 1024 + tid;
    int v = (i < n) ? g_cnt[i] : 0;
    sd[tid] = v;
    __syncthreads();
    #pragma unroll
    for (int off = 1; off < 1024; off <<= 1) {
        int t = (tid >= off) ? sd[tid - off] : 0;
        __syncthreads();
        sd[tid] += t;
        __syncthreads();
    }
    if (i < n) g_off[i] = sd[tid] - v;
    if (tid == 1023) g_bsum[blockIdx.x] = sd[1023];
}
__global__ void s2_scan(int nb) {
    if (threadIdx.x == 0) {
        int acc = 0;
        for (int b = 0; b < nb; b++) { int t = g_bsum[b]; g_boff[b] = acc; acc += t; }
    }
}
__global__ void s3_scan(int n, int E) {
    int i = blockIdx.x * 1024 + threadIdx.x;
    if (i < n) {
        int v = g_off[i] + g_boff[blockIdx.x];
        g_off[i] = v;
        g_cur[i] = v;
    }
    if (i == 0) g_off[n] = E;
}

// ============ KC3W1: CSR fill + layer-1 softmax numerators ============
__global__ void kc3w1(const void* __restrict__ ei, int E) {
    int i = blockIdx.x * blockDim.x + threadIdx.x;
    if (i >= E) return;
    int s, d; load_edge(ei, E, i, s, d);
    int p = atomicAdd(&g_cur[d], 1);
    g_csrc[p] = s;
    float4 as = *reinterpret_cast<const float4*>(g_as1 + 4 * s);
    float4 ad = *reinterpret_cast<const float4*>(g_ad1 + 4 * d);
    float4 w;
    w.x = lrelu_exp(as.x + ad.x);
    w.y = lrelu_exp(as.y + ad.y);
    w.z = lrelu_exp(as.z + ad.z);
    w.w = lrelu_exp(as.w + ad.w);
    *reinterpret_cast<float4*>(g_w1 + (size_t)p * 4) = w;
}

// ============ KA1: gather aggregation, layer 1 (fp16 rows, half2/thread) ====
__global__ void ka1(int n_nodes) {
    __shared__ int   ssrc[128];
    __shared__ float sw[128 * 4];
    const int d = blockIdx.x;
    const int j = threadIdx.x;        // 128: features 2j, 2j+1
    const int h = j >> 5;             // head of feature 2j
    float w0 = lrelu_exp(g_as1[d * NHEADS + h] + g_ad1[d * NHEADS + h]);
    float den = w0;
    float2 acc;
    {
        float2 hv = __half22float2(
            reinterpret_cast<const __half2*>(g_h1 + (size_t)d * HH)[j]);
        acc.x = w0 * hv.x; acc.y = w0 * hv.y;
    }
    const int pB = g_off[d], pE = g_off[d + 1];
    for (int p0 = pB; p0 < pE; p0 += 128) {
        int np = min(128, pE - p0);
        __syncthreads();
        if (j < np) {
            ssrc[j] = g_csrc[p0 + j];
            *reinterpret_cast<float4*>(&sw[4 * j]) =
                *reinterpret_cast<const float4*>(g_w1 + (size_t)(p0 + j) * 4);
        }
        __syncthreads();
        #pragma unroll 4
        for (int e = 0; e < np; e++) {
            int s = ssrc[e];
            float wp = sw[4 * e + h];
            den += wp;
            float2 hv = __half22float2(
                reinterpret_cast<const __half2*>(g_h1 + (size_t)s * HH)[j]);
            acc.x += wp * hv.x; acc.y += wp * hv.y;
        }
    }
    *reinterpret_cast<float2*>(g_agg1 + (size_t)d * HH + 2 * j) =
        make_float2(acc.x / den, acc.y / den);
}

// ============ K4: h2 = elu(agg1+b1) @ W2 (MMA, 2 k-chunks) + logits ========
#define K4_XPAD  136
#define K4_WPAD  72
#define K4_XSZ   (64 * K4_XPAD)
#define K4_WSZ   (128 * K4_WPAD)
#define K4_SMEM  ((2 * K4_XSZ + 2 * K4_WSZ) * 2 + HH * 2 * 4)
__global__ void k4_gemm2(const float* __restrict__ W2, const float* __restrict__ b1,
                         int n_nodes) {
    extern __shared__ __nv_bfloat16 smb[];
    __nv_bfloat16* Xhi = smb;
    __nv_bfloat16* Xlo = smb + K4_XSZ;
    __nv_bfloat16* Whi = smb + 2 * K4_XSZ;
    __nv_bfloat16* Wlo = smb + 2 * K4_XSZ + K4_WSZ;
    float* swa = reinterpret_cast<float*>(smb + 2 * K4_XSZ + 2 * K4_WSZ);
    const int n0 = blockIdx.x * 64;
    const int c0 = blockIdx.y * 64;
    const int tid = threadIdx.x;      // 128
    const bool do_logits = (blockIdx.y == 0);
    if (do_logits) for (int i = tid; i < HH * 2; i += 128) swa[i] = g_wa2[i];

    const int wid = tid >> 5, lane = tid & 31;
    const int wr = (wid & 1) * 32;
    const int wc = (wid >> 1) * 32;
    const int gq = lane >> 2, tg = lane & 3;

    unsigned aAhi[2], aAlo[2];
    {
        const int ak = (lane >> 4) * 8;
        #pragma unroll
        for (int rg = 0; rg < 2; rg++) {
            int row = wr + rg * 16 + (lane & 15);
            aAhi[rg] = sm_u32(Xhi + row * K4_XPAD + ak);
            aAlo[rg] = sm_u32(Xlo + row * K4_XPAD + ak);
        }
    }
    unsigned aBhi = sm_u32(Whi + (lane & 15) * K4_WPAD + wc);
    unsigned aBlo = sm_u32(Wlo + (lane & 15) * K4_WPAD + wc);

    float C[2][4][4] = {};
    float ls = 0.f;
    #pragma unroll
    for (int kc = 0; kc < 2; kc++) {
        const int kbase = kc * 128;
        __syncthreads();
        #pragma unroll
        for (int r = 0; r < 16; r++) {
            int i = tid + r * 128;
            int nn = i >> 5, k4 = i & 31;
            int g = n0 + nn;
            float4 v = make_float4(0.f, 0.f, 0.f, 0.f);
            if (g < n_nodes) {
                int kk = kbase + 4 * k4;
                v = *reinterpret_cast<const float4*>(g_agg1 + (size_t)g * HH + kk);
                float4 b = *reinterpret_cast<const float4*>(b1 + kk);
                v.x += b.x; v.y += b.y; v.z += b.z; v.w += b.w;
                v.x = v.x > 0.f ? v.x : expm1f(v.x);
                v.y = v.y > 0.f ? v.y : expm1f(v.y);
                v.z = v.z > 0.f ? v.z : expm1f(v.z);
                v.w = v.w > 0.f ? v.w : expm1f(v.w);
            }
            uint2 hp, lp;
            hp.x = bf16_hi_pack(v.x, v.y); hp.y = bf16_hi_pack(v.z, v.w);
            lp.x = bf16_lo_pack(v.x, v.y); lp.y = bf16_lo_pack(v.z, v.w);
            *reinterpret_cast<uint2*>(&Xhi[nn * K4_XPAD + 4 * k4]) = hp;
            *reinterpret_cast<uint2*>(&Xlo[nn * K4_XPAD + 4 * k4]) = lp;
        }
        #pragma unroll
        for (int r = 0; r < 16; r++) {
            int i = tid + r * 128;
            int k = i >> 4, c4 = i & 15;
            float4 w = *reinterpret_cast<const float4*>(
                W2 + (size_t)(kbase + k) * OUT2 + c0 + 4 * c4);
            uint2 hp, lp;
            hp.x = bf16_hi_pack(w.x, w.y); hp.y = bf16_hi_pack(w.z, w.w);
            lp.x = bf16_lo_pack(w.x, w.y); lp.y = bf16_lo_pack(w.z, w.w);
            *reinterpret_cast<uint2*>(&Whi[k * K4_WPAD + 4 * c4]) = hp;
            *reinterpret_cast<uint2*>(&Wlo[k * K4_WPAD + 4 * c4]) = lp;
        }
        __syncthreads();
        if (do_logits) {
            int nn = tid >> 1, o = tid & 1;
            #pragma unroll 8
            for (int k = 0; k < 128; k++) {
                float xvv = __bfloat162float(Xhi[nn * K4_XPAD + k]) +
                            __bfloat162float(Xlo[nn * K4_XPAD + k]);
                ls += xvv * swa[2 * (kbase + k) + o];
            }
        }
        #pragma unroll
        for (int ks = 0; ks < 8; ks++) {
            const unsigned koffA = ks * 32;
            const unsigned koffB = ks * 16 * K4_WPAD * 2;
            unsigned ah[2][4], al[2][4];
            #pragma unroll
            for (int rg = 0; rg < 2; rg++) {
                LDSM4(ah[rg][0], ah[rg][1], ah[rg][2], ah[rg][3], aAhi[rg] + koffA);
                LDSM4(al[rg][0], al[rg][1], al[rg][2], al[rg][3], aAlo[rg] + koffA);
            }
            #pragma unroll
            for (int ns = 0; ns < 4; ns++) {
                unsigned bh0, bh1, bl0, bl1;
                LDSM2T(bh0, bh1, aBhi + koffB + ns * 16);
                LDSM2T(bl0, bl1, aBlo + koffB + ns * 16);
                #pragma unroll
                for (int rg = 0; rg < 2; rg++) {
                    MMA_BF16(C[rg][ns][0], C[rg][ns][1], C[rg][ns][2], C[rg][ns][3],
                             ah[rg][0], ah[rg][1], ah[rg][2], ah[rg][3], bh0, bh1);
                    MMA_BF16(C[rg][ns][0], C[rg][ns][1], C[rg][ns][2], C[rg][ns][3],
                             ah[rg][0], ah[rg][1], ah[rg][2], ah[rg][3], bl0, bl1);
                    MMA_BF16(C[rg][ns][0], C[rg][ns][1], C[rg][ns][2], C[rg][ns][3],
                             al[rg][0], al[rg][1], al[rg][2], al[rg][3], bh0, bh1);
                }
            }
        }
    }
    #pragma unroll
    for (int rg = 0; rg < 2; rg++) {
        #pragma unroll
        for (int ns = 0; ns < 4; ns++) {
            int col = c0 + wc + ns * 8 + 2 * tg;
            int r0 = n0 + wr + rg * 16 + gq;
            if (r0 < n_nodes)
                *reinterpret_cast<__half2*>(g_h2 + (size_t)r0 * OUT2 + col) =
                    __floats2half2_rn(C[rg][ns][0], C[rg][ns][1]);
            if (r0 + 8 < n_nodes)
                *reinterpret_cast<__half2*>(g_h2 + (size_t)(r0 + 8) * OUT2 + col) =
                    __floats2half2_rn(C[rg][ns][2], C[rg][ns][3]);
        }
    }
    if (do_logits) {
        int nn = tid >> 1, o = tid & 1;
        int g = n0 + nn;
        if (g < n_nodes) {
            if (o == 0) g_as2[g] = ls;
            else        g_ad2[g] = ls;
        }
    }
}

// ============ KA2: gather aggregation, layer 2 (fp16 rows, 64 thr) ==========
__global__ void ka2(int n_nodes, const float* __restrict__ b2,
                    float* __restrict__ out) {
    __shared__ int   ssrc[64];
    __shared__ float sw[64];
    const int d = blockIdx.x;
    const int j = threadIdx.x;   // 64: features 2j, 2j+1
    float add = g_ad2[d];
    float w0 = lrelu_exp(g_as2[d] + add);
    float den = w0;
    float2 acc;
    {
        float2 hv = __half22float2(
            reinterpret_cast<const __half2*>(g_h2 + (size_t)d * OUT2)[j]);
        acc.x = w0 * hv.x; acc.y = w0 * hv.y;
    }
    const int pB = g_off[d], pE = g_off[d + 1];
    for (int p0 = pB; p0 < pE; p0 += 64) {
        int np = min(64, pE - p0);
        __syncthreads();
        if (j < np) {
            int s = g_csrc[p0 + j];
            ssrc[j] = s;
            sw[j] = lrelu_exp(g_as2[s] + add);
        }
        __syncthreads();
        #pragma unroll 4
        for (int e = 0; e < np; e++) {
            int s = ssrc[e];
            float wp = sw[e];
            den += wp;
            float2 hv = __half22float2(
                reinterpret_cast<const __half2*>(g_h2 + (size_t)s * OUT2)[j]);
            acc.x += wp * hv.x; acc.y += wp * hv.y;
        }
    }
    float2 bb = *reinterpret_cast<const float2*>(b2 + 2 * j);
    *reinterpret_cast<float2*>(out + (size_t)d * OUT2 + 2 * j) =
        make_float2(acc.x / den + bb.x, acc.y / den + bb.y);
}

extern "C" void kernel_launch(void* const* d_in, const int* in_sizes, int n_in,
                              void* d_out, int out_size) {
    const float* x    = (const float*)d_in[0];
    const void*  ei   = d_in[1];
    const float* W1   = (const float*)d_in[2];
    const float* as1  = (const float*)d_in[3];
    const float* ad1  = (const float*)d_in[4];
    const float* b1   = (const float*)d_in[5];
    const float* W2   = (const float*)d_in[6];
    const float* as2  = (const float*)d_in[7];
    const float* ad2  = (const float*)d_in[8];
    const float* b2   = (const float*)d_in[9];
    float* out = (float*)d_out;

    const int n_nodes = in_sizes[0] / NF;
    const int E  = in_sizes[1] / 2;

    const int eb = (E + 255) / 256;
    const int nb = (n_nodes + 1023) / 1024;

    static int smem_set = 0;
    if (!smem_set) {
        cudaFuncSetAttribute(k1_gemm1, cudaFuncAttributeMaxDynamicSharedMemorySize, K1_SMEM);
        cudaFuncSetAttribute(k4_gemm2, cudaFuncAttributeMaxDynamicSharedMemorySize, K4_SMEM);
        smem_set = 1;
    }

    dim3 g1((n_nodes + 63) / 64, HH / 64);      // 782 x 4
    dim3 g4((n_nodes + 63) / 64, OUT2 / 64);    // 782 x 2

    kz<<<nb + 1, 1024>>>((const int*)ei, E, n_nodes);          // 1
    kc2_count<<<eb, 256>>>(ei, E);                             // 2
    kv<<<6, 256>>>(W1, as1, ad1, W2, as2, ad2);                // 3
    k1_gemm1<<<g1, 128, K1_SMEM>>>(x, W1, n_nodes);            // 4  <- profiled slot
    s1_scan<<<nb, 1024>>>(n_nodes);                            // 5
    s2_scan<<<1, 32>>>(nb);                                    // 6
    s3_scan<<<nb, 1024>>>(n_nodes, E);                         // 7
    kc3w1<<<eb, 256>>>(ei, E);                                 // 8
    ka1<<<n_nodes, 128>>>(n_nodes);                            // 9
    k4_gemm2<<<g4, 128, K4_SMEM>>>(W2, b1, n_nodes);           // 10
    ka2<<<n_nodes, 64>>>(n_nodes, b2, out);                    // 11
}

// round 13
// speedup vs baseline: 1.6810x; 1.0107x over previous
#include <cuda_runtime.h>
#include <cuda_bf16.h>
#include <cuda_fp16.h>

#define NMAX   50016
#define EMAX   800000
#define NF     128
#define HH     256
#define OUT2   128
#define NHEADS 4
#define NEG    0.2f

// ---- scratch ----
__device__ __half g_h1[(size_t)NMAX * HH];     // fp16 layer-1 features
__device__ __half g_agg1h[(size_t)NMAX * HH];  // fp16 aggregated layer-1
__device__ __half g_h2[(size_t)NMAX * OUT2];   // fp16 layer-2 features
__device__ float g_as1[NMAX * NHEADS];
__device__ float g_ad1[NMAX * NHEADS];
__device__ float g_as2[NMAX];
__device__ float g_ad2[NMAX];
__device__ float g_va1[NF * 8];
__device__ float g_wa2[HH * 2];
__device__ int   g_is64;
// CSR
__device__ int   g_cnt [NMAX + 1];
__device__ int   g_off [NMAX + 1];
__device__ int   g_cur [NMAX + 1];
__device__ int   g_bsum[64];
__device__ int   g_boff[64];
__device__ int   g_csrc[EMAX];
__device__ float g_w1  [(size_t)EMAX * NHEADS];

__device__ __forceinline__ void load_edge(const void* ei, int E, int i,
                                          int& s, int& d) {
    if (g_is64) {
        const long long* p = (const long long*)ei;
        s = (int)p[i]; d = (int)p[(size_t)E + i];
    } else {
        const int* p = (const int*)ei;
        s = p[i]; d = p[E + i];
    }
}

__device__ __forceinline__ float lrelu_exp(float v) {
    v = v > 0.f ? v : NEG * v;
    return __expf(v);
}

#define MMA_BF16(c0,c1,c2,c3,a0,a1,a2,a3,b0,b1) \
    asm("mma.sync.aligned.m16n8k16.row.col.f32.bf16.bf16.f32 " \
        "{%0,%1,%2,%3}, {%4,%5,%6,%7}, {%8,%9}, {%0,%1,%2,%3};" \
        : "+f"(c0), "+f"(c1), "+f"(c2), "+f"(c3) \
        : "r"(a0), "r"(a1), "r"(a2), "r"(a3), "r"(b0), "r"(b1))

#define LDSM4(R0,R1,R2,R3,A) \
    asm volatile("ldmatrix.sync.aligned.m8n8.x4.shared.b16 {%0,%1,%2,%3}, [%4];" \
        : "=r"(R0), "=r"(R1), "=r"(R2), "=r"(R3) : "r"(A))
#define LDSM2T(R0,R1,A) \
    asm volatile("ldmatrix.sync.aligned.m8n8.x2.trans.shared.b16 {%0,%1}, [%2];" \
        : "=r"(R0), "=r"(R1) : "r"(A))

__device__ __forceinline__ unsigned sm_u32(const void* p) {
    return (unsigned)__cvta_generic_to_shared(p);
}

__device__ __forceinline__ unsigned bf16_hi_pack(float a, float b) {
    unsigned ua = (unsigned)__bfloat16_as_ushort(__float2bfloat16(a));
    unsigned ub = (unsigned)__bfloat16_as_ushort(__float2bfloat16(b));
    return ua | (ub << 16);
}
__device__ __forceinline__ unsigned bf16_lo_pack(float a, float b) {
    float ra = a - __bfloat162float(__float2bfloat16(a));
    float rb = b - __bfloat162float(__float2bfloat16(b));
    return bf16_hi_pack(ra, rb);
}

// ============ KZ: dtype probe + zero counts ============
__global__ void kz(const int* ei32, int E, int n) {
    int i = blockIdx.x * 1024 + threadIdx.x;
    if (i <= n) g_cnt[i] = 0;
    if (blockIdx.x == 0) {
        __shared__ int flag;
        if (threadIdx.x == 0) flag = 0;
        __syncthreads();
        for (int j = threadIdx.x; j < 2048; j += 1024) {
            int idx = 2 * j + 1;
            if (idx < 2 * E && ei32[idx] != 0) flag = 1;
        }
        __syncthreads();
        if (threadIdx.x == 0) g_is64 = (flag == 0);
    }
}

// ============ KC2: count in-degrees ============
__global__ void kc2_count(const void* __restrict__ ei, int E) {
    int i = blockIdx.x * blockDim.x + threadIdx.x;
    if (i >= E) return;
    int s, d; load_edge(ei, E, i, s, d);
    atomicAdd(&g_cnt[d], 1);
}

// ============ KV: attention-vector precomputes ============
__global__ void kv(const float* __restrict__ W1, const float* __restrict__ a_s1,
                   const float* __restrict__ a_d1, const float* __restrict__ W2,
                   const float* __restrict__ a_s2, const float* __restrict__ a_d2) {
    int t = blockIdx.x * 256 + threadIdx.x;
    if (t < NF * 8) {
        int k = t >> 3, o = t & 7, h = o & 3;
        const float* a = (o < 4 ? a_s1 : a_d1) + h * 64;
        const float* w = W1 + (size_t)k * HH + h * 64;
        float s = 0.f;
        #pragma unroll 8
        for (int c = 0; c < 64; c++) s += w[c] * a[c];
        g_va1[t] = s;
    } else if (t < NF * 8 + HH * 2) {
        int q = t - NF * 8;
        int k = q >> 1, o = q & 1;
        const float* a = o ? a_d2 : a_s2;
        const float* w = W2 + (size_t)k * OUT2;
        float s = 0.f;
        #pragma unroll 8
        for (int c = 0; c < OUT2; c++) s += w[c] * a[c];
        g_wa2[q] = s;
    }
}

// ==== shared GEMM chunk geometry: 64 rows x 64 cols x 64-k chunks ====
#define CH_PAD  72
#define CH_SZ   (64 * CH_PAD)

// ============ K1: h1 = x @ W1  (chunked bf16-split MMA) + logits ============
#define K1_SMEM (4 * CH_SZ * 2 + NF * 8 * 4)     // 36864 + 4096
__global__ void k1_gemm1(const float* __restrict__ x, const float* __restrict__ W1,
                         int n_nodes) {
    extern __shared__ __nv_bfloat16 smb[];
    __nv_bfloat16* Xhi = smb;
    __nv_bfloat16* Xlo = smb + CH_SZ;
    __nv_bfloat16* Whi = smb + 2 * CH_SZ;
    __nv_bfloat16* Wlo = smb + 3 * CH_SZ;
    float* sva = reinterpret_cast<float*>(smb + 4 * CH_SZ);
    const int n0 = blockIdx.x * 64;
    const int c0 = blockIdx.y * 64;
    const int tid = threadIdx.x;                    // 128
    const bool do_logits = (blockIdx.y == 0);
    if (do_logits) for (int i = tid; i < NF * 8; i += 128) sva[i] = g_va1[i];

    const int wid = tid >> 5, lane = tid & 31;
    const int wr = (wid & 1) * 32;
    const int wc = (wid >> 1) * 32;
    const int gq = lane >> 2, tg = lane & 3;

    unsigned aAhi[2], aAlo[2];
    {
        const int ak = (lane >> 4) * 8;
        #pragma unroll
        for (int rg = 0; rg < 2; rg++) {
            int row = wr + rg * 16 + (lane & 15);
            aAhi[rg] = sm_u32(Xhi + row * CH_PAD + ak);
            aAlo[rg] = sm_u32(Xlo + row * CH_PAD + ak);
        }
    }
    unsigned aBhi = sm_u32(Whi + (lane & 15) * CH_PAD + wc);
    unsigned aBlo = sm_u32(Wlo + (lane & 15) * CH_PAD + wc);

    float C[2][4][4] = {};
    float s0 = 0.f, s1 = 0.f, s2 = 0.f, s3 = 0.f;   // logits accum
    #pragma unroll
    for (int kc = 0; kc < 2; kc++) {
        const int kbase = kc * 64;
        __syncthreads();
        // stage X chunk (64 rows x 64 k)
        #pragma unroll
        for (int r = 0; r < 8; r++) {
            int i = tid + r * 128;
            int nn = i >> 4, k4 = i & 15;
            int g = n0 + nn;
            float4 v = make_float4(0.f, 0.f, 0.f, 0.f);
            if (g < n_nodes)
                v = *reinterpret_cast<const float4*>(x + (size_t)g * NF + kbase + 4 * k4);
            uint2 hp, lp;
            hp.x = bf16_hi_pack(v.x, v.y); hp.y = bf16_hi_pack(v.z, v.w);
            lp.x = bf16_lo_pack(v.x, v.y); lp.y = bf16_lo_pack(v.z, v.w);
            *reinterpret_cast<uint2*>(&Xhi[nn * CH_PAD + 4 * k4]) = hp;
            *reinterpret_cast<uint2*>(&Xlo[nn * CH_PAD + 4 * k4]) = lp;
        }
        // stage W chunk (64 k x 64 cols), k-major
        #pragma unroll
        for (int r = 0; r < 8; r++) {
            int i = tid + r * 128;
            int k = i >> 4, c4 = i & 15;
            float4 w = *reinterpret_cast<const float4*>(
                W1 + (size_t)(kbase + k) * HH + c0 + 4 * c4);
            uint2 hp, lp;
            hp.x = bf16_hi_pack(w.x, w.y); hp.y = bf16_hi_pack(w.z, w.w);
            lp.x = bf16_lo_pack(w.x, w.y); lp.y = bf16_lo_pack(w.z, w.w);
            *reinterpret_cast<uint2*>(&Whi[k * CH_PAD + 4 * c4]) = hp;
            *reinterpret_cast<uint2*>(&Wlo[k * CH_PAD + 4 * c4]) = lp;
        }
        __syncthreads();
        // fused layer-1 logits partial (64 nodes x 2 quads)
        if (do_logits) {
            int nn = tid >> 1, o4 = (tid & 1) * 4;
            #pragma unroll 8
            for (int k = 0; k < 64; k++) {
                float xv = __bfloat162float(Xhi[nn * CH_PAD + k]) +
                           __bfloat162float(Xlo[nn * CH_PAD + k]);
                const float* sv = sva + (kbase + k) * 8 + o4;
                s0 += xv * sv[0]; s1 += xv * sv[1];
                s2 += xv * sv[2]; s3 += xv * sv[3];
            }
        }
        // MMA over chunk (4 k16 steps)
        #pragma unroll
        for (int ks = 0; ks < 4; ks++) {
            const unsigned koffA = ks * 32;
            const unsigned koffB = ks * 16 * CH_PAD * 2;
            unsigned ah[2][4], al[2][4];
            #pragma unroll
            for (int rg = 0; rg < 2; rg++) {
                LDSM4(ah[rg][0], ah[rg][1], ah[rg][2], ah[rg][3], aAhi[rg] + koffA);
                LDSM4(al[rg][0], al[rg][1], al[rg][2], al[rg][3], aAlo[rg] + koffA);
            }
            #pragma unroll
            for (int ns = 0; ns < 4; ns++) {
                unsigned bh0, bh1, bl0, bl1;
                LDSM2T(bh0, bh1, aBhi + koffB + ns * 16);
                LDSM2T(bl0, bl1, aBlo + koffB + ns * 16);
                #pragma unroll
                for (int rg = 0; rg < 2; rg++) {
                    MMA_BF16(C[rg][ns][0], C[rg][ns][1], C[rg][ns][2], C[rg][ns][3],
                             ah[rg][0], ah[rg][1], ah[rg][2], ah[rg][3], bh0, bh1);
                    MMA_BF16(C[rg][ns][0], C[rg][ns][1], C[rg][ns][2], C[rg][ns][3],
                             ah[rg][0], ah[rg][1], ah[rg][2], ah[rg][3], bl0, bl1);
                    MMA_BF16(C[rg][ns][0], C[rg][ns][1], C[rg][ns][2], C[rg][ns][3],
                             al[rg][0], al[rg][1], al[rg][2], al[rg][3], bh0, bh1);
                }
            }
        }
    }
    #pragma unroll
    for (int rg = 0; rg < 2; rg++) {
        #pragma unroll
        for (int ns = 0; ns < 4; ns++) {
            int col = c0 + wc + ns * 8 + 2 * tg;
            int r0 = n0 + wr + rg * 16 + gq;
            if (r0 < n_nodes)
                *reinterpret_cast<__half2*>(g_h1 + (size_t)r0 * HH + col) =
                    __floats2half2_rn(C[rg][ns][0], C[rg][ns][1]);
            if (r0 + 8 < n_nodes)
                *reinterpret_cast<__half2*>(g_h1 + (size_t)(r0 + 8) * HH + col) =
                    __floats2half2_rn(C[rg][ns][2], C[rg][ns][3]);
        }
    }
    if (do_logits) {
        int nn = tid >> 1, o4 = (tid & 1) * 4;
        int g = n0 + nn;
        if (g < n_nodes) {
            float* dst = (o4 == 0 ? g_as1 : g_ad1) + g * 4;
            *reinterpret_cast<float4*>(dst) = make_float4(s0, s1, s2, s3);
        }
    }
}

// ============ scan ============
__global__ void s1_scan(int n) {
    __shared__ int sd[1024];
    int tid = threadIdx.x;
    int i = blockIdx.x * 1024 + tid;
    int v = (i < n) ? g_cnt[i] : 0;
    sd[tid] = v;
    __syncthreads();
    #pragma unroll
    for (int off = 1; off < 1024; off <<= 1) {
        int t = (tid >= off) ? sd[tid - off] : 0;
        __syncthreads();
        sd[tid] += t;
        __syncthreads();
    }
    if (i < n) g_off[i] = sd[tid] - v;
    if (tid == 1023) g_bsum[blockIdx.x] = sd[1023];
}
__global__ void s2_scan(int nb) {
    if (threadIdx.x == 0) {
        int acc = 0;
        for (int b = 0; b < nb; b++) { int t = g_bsum[b]; g_boff[b] = acc; acc += t; }
    }
}
__global__ void s3_scan(int n, int E) {
    int i = blockIdx.x * 1024 + threadIdx.x;
    if (i < n) {
        int v = g_off[i] + g_boff[blockIdx.x];
        g_off[i] = v;
        g_cur[i] = v;
    }
    if (i == 0) g_off[n] = E;
}

// ============ KC3W1: CSR fill + layer-1 softmax numerators ============
__global__ void kc3w1(const void* __restrict__ ei, int E) {
    int i = blockIdx.x * blockDim.x + threadIdx.x;
    if (i >= E) return;
    int s, d; load_edge(ei, E, i, s, d);
    int p = atomicAdd(&g_cur[d], 1);
    g_csrc[p] = s;
    float4 as = *reinterpret_cast<const float4*>(g_as1 + 4 * s);
    float4 ad = *reinterpret_cast<const float4*>(g_ad1 + 4 * d);
    float4 w;
    w.x = lrelu_exp(as.x + ad.x);
    w.y = lrelu_exp(as.y + ad.y);
    w.z = lrelu_exp(as.z + ad.z);
    w.w = lrelu_exp(as.w + ad.w);
    *reinterpret_cast<float4*>(g_w1 + (size_t)p * 4) = w;
}

// ============ KA1: gather aggregation, layer 1 (fp16 in, fp16 out) ==========
__global__ void ka1(int n_nodes) {
    __shared__ int   ssrc[128];
    __shared__ float sw[128 * 4];
    const int d = blockIdx.x;
    const int j = threadIdx.x;        // 128: features 2j, 2j+1
    const int h = j >> 5;             // head of feature 2j
    float w0 = lrelu_exp(g_as1[d * NHEADS + h] + g_ad1[d * NHEADS + h]);
    float den = w0;
    float2 acc;
    {
        float2 hv = __half22float2(
            reinterpret_cast<const __half2*>(g_h1 + (size_t)d * HH)[j]);
        acc.x = w0 * hv.x; acc.y = w0 * hv.y;
    }
    const int pB = g_off[d], pE = g_off[d + 1];
    for (int p0 = pB; p0 < pE; p0 += 128) {
        int np = min(128, pE - p0);
        __syncthreads();
        if (j < np) {
            ssrc[j] = g_csrc[p0 + j];
            *reinterpret_cast<float4*>(&sw[4 * j]) =
                *reinterpret_cast<const float4*>(g_w1 + (size_t)(p0 + j) * 4);
        }
        __syncthreads();
        #pragma unroll 4
        for (int e = 0; e < np; e++) {
            int s = ssrc[e];
            float wp = sw[4 * e + h];
            den += wp;
            float2 hv = __half22float2(
                reinterpret_cast<const __half2*>(g_h1 + (size_t)s * HH)[j]);
            acc.x += wp * hv.x; acc.y += wp * hv.y;
        }
    }
    reinterpret_cast<__half2*>(g_agg1h + (size_t)d * HH)[j] =
        __floats2half2_rn(acc.x / den, acc.y / den);
}

// ============ K4: h2 = elu(agg1+b1) @ W2 (chunked MMA) + layer-2 logits =====
#define K4_SMEM (4 * CH_SZ * 2 + HH * 2 * 4)     // 36864 + 2048
__global__ void k4_gemm2(const float* __restrict__ W2, const float* __restrict__ b1,
                         int n_nodes) {
    extern __shared__ __nv_bfloat16 smb[];
    __nv_bfloat16* Xhi = smb;
    __nv_bfloat16* Xlo = smb + CH_SZ;
    __nv_bfloat16* Whi = smb + 2 * CH_SZ;
    __nv_bfloat16* Wlo = smb + 3 * CH_SZ;
    float* swa = reinterpret_cast<float*>(smb + 4 * CH_SZ);
    const int n0 = blockIdx.x * 64;
    const int c0 = blockIdx.y * 64;
    const int tid = threadIdx.x;      // 128
    const bool do_logits = (blockIdx.y == 0);
    if (do_logits) for (int i = tid; i < HH * 2; i += 128) swa[i] = g_wa2[i];

    const int wid = tid >> 5, lane = tid & 31;
    const int wr = (wid & 1) * 32;
    const int wc = (wid >> 1) * 32;
    const int gq = lane >> 2, tg = lane & 3;

    unsigned aAhi[2], aAlo[2];
    {
        const int ak = (lane >> 4) * 8;
        #pragma unroll
        for (int rg = 0; rg < 2; rg++) {
            int row = wr + rg * 16 + (lane & 15);
            aAhi[rg] = sm_u32(Xhi + row * CH_PAD + ak);
            aAlo[rg] = sm_u32(Xlo + row * CH_PAD + ak);
        }
    }
    unsigned aBhi = sm_u32(Whi + (lane & 15) * CH_PAD + wc);
    unsigned aBlo = sm_u32(Wlo + (lane & 15) * CH_PAD + wc);

    float C[2][4][4] = {};
    float ls = 0.f;
    #pragma unroll
    for (int kc = 0; kc < 4; kc++) {
        const int kbase = kc * 64;
        __syncthreads();
        // stage X chunk: elu(agg1h + b1), hi/lo split
        #pragma unroll
        for (int r = 0; r < 8; r++) {
            int i = tid + r * 128;
            int nn = i >> 4, k4 = i & 15;
            int g = n0 + nn;
            float4 v = make_float4(0.f, 0.f, 0.f, 0.f);
            if (g < n_nodes) {
                int kk = kbase + 4 * k4;
                uint2 raw = *reinterpret_cast<const uint2*>(g_agg1h + (size_t)g * HH + kk);
                float2 f01 = __half22float2(*reinterpret_cast<__half2*>(&raw.x));
                float2 f23 = __half22float2(*reinterpret_cast<__half2*>(&raw.y));
                float4 b = *reinterpret_cast<const float4*>(b1 + kk);
                v.x = f01.x + b.x; v.y = f01.y + b.y;
                v.z = f23.x + b.z; v.w = f23.y + b.w;
                v.x = v.x > 0.f ? v.x : expm1f(v.x);
                v.y = v.y > 0.f ? v.y : expm1f(v.y);
                v.z = v.z > 0.f ? v.z : expm1f(v.z);
                v.w = v.w > 0.f ? v.w : expm1f(v.w);
            }
            uint2 hp, lp;
            hp.x = bf16_hi_pack(v.x, v.y); hp.y = bf16_hi_pack(v.z, v.w);
            lp.x = bf16_lo_pack(v.x, v.y); lp.y = bf16_lo_pack(v.z, v.w);
            *reinterpret_cast<uint2*>(&Xhi[nn * CH_PAD + 4 * k4]) = hp;
            *reinterpret_cast<uint2*>(&Xlo[nn * CH_PAD + 4 * k4]) = lp;
        }
        // stage W chunk k-major
        #pragma unroll
        for (int r = 0; r < 8; r++) {
            int i = tid + r * 128;
            int k = i >> 4, c4 = i & 15;
            float4 w = *reinterpret_cast<const float4*>(
                W2 + (size_t)(kbase + k) * OUT2 + c0 + 4 * c4);
            uint2 hp, lp;
            hp.x = bf16_hi_pack(w.x, w.y); hp.y = bf16_hi_pack(w.z, w.w);
            lp.x = bf16_lo_pack(w.x, w.y); lp.y = bf16_lo_pack(w.z, w.w);
            *reinterpret_cast<uint2*>(&Whi[k * CH_PAD + 4 * c4]) = hp;
            *reinterpret_cast<uint2*>(&Wlo[k * CH_PAD + 4 * c4]) = lp;
        }
        __syncthreads();
        if (do_logits) {
            int nn = tid >> 1, o = tid & 1;
            #pragma unroll 8
            for (int k = 0; k < 64; k++) {
                float xvv = __bfloat162float(Xhi[nn * CH_PAD + k]) +
                            __bfloat162float(Xlo[nn * CH_PAD + k]);
                ls += xvv * swa[2 * (kbase + k) + o];
            }
        }
        #pragma unroll
        for (int ks = 0; ks < 4; ks++) {
            const unsigned koffA = ks * 32;
            const unsigned koffB = ks * 16 * CH_PAD * 2;
            unsigned ah[2][4], al[2][4];
            #pragma unroll
            for (int rg = 0; rg < 2; rg++) {
                LDSM4(ah[rg][0], ah[rg][1], ah[rg][2], ah[rg][3], aAhi[rg] + koffA);
                LDSM4(al[rg][0], al[rg][1], al[rg][2], al[rg][3], aAlo[rg] + koffA);
            }
            #pragma unroll
            for (int ns = 0; ns < 4; ns++) {
                unsigned bh0, bh1, bl0, bl1;
                LDSM2T(bh0, bh1, aBhi + koffB + ns * 16);
                LDSM2T(bl0, bl1, aBlo + koffB + ns * 16);
                #pragma unroll
                for (int rg = 0; rg < 2; rg++) {
                    MMA_BF16(C[rg][ns][0], C[rg][ns][1], C[rg][ns][2], C[rg][ns][3],
                             ah[rg][0], ah[rg][1], ah[rg][2], ah[rg][3], bh0, bh1);
                    MMA_BF16(C[rg][ns][0], C[rg][ns][1], C[rg][ns][2], C[rg][ns][3],
                             ah[rg][0], ah[rg][1], ah[rg][2], ah[rg][3], bl0, bl1);
                    MMA_BF16(C[rg][ns][0], C[rg][ns][1], C[rg][ns][2], C[rg][ns][3],
                             al[rg][0], al[rg][1], al[rg][2], al[rg][3], bh0, bh1);
                }
            }
        }
    }
    #pragma unroll
    for (int rg = 0; rg < 2; rg++) {
        #pragma unroll
        for (int ns = 0; ns < 4; ns++) {
            int col = c0 + wc + ns * 8 + 2 * tg;
            int r0 = n0 + wr + rg * 16 + gq;
            if (r0 < n_nodes)
                *reinterpret_cast<__half2*>(g_h2 + (size_t)r0 * OUT2 + col) =
                    __floats2half2_rn(C[rg][ns][0], C[rg][ns][1]);
            if (r0 + 8 < n_nodes)
                *reinterpret_cast<__half2*>(g_h2 + (size_t)(r0 + 8) * OUT2 + col) =
                    __floats2half2_rn(C[rg][ns][2], C[rg][ns][3]);
        }
    }
    if (do_logits) {
        int nn = tid >> 1, o = tid & 1;
        int g = n0 + nn;
        if (g < n_nodes) {
            if (o == 0) g_as2[g] = ls;
            else        g_ad2[g] = ls;
        }
    }
}

// ============ KA2: gather aggregation, layer 2 (fp16 rows, 64 thr) ==========
__global__ void ka2(int n_nodes, const float* __restrict__ b2,
                    float* __restrict__ out) {
    __shared__ int   ssrc[64];
    __shared__ float sw[64];
    const int d = blockIdx.x;
    const int j = threadIdx.x;   // 64: features 2j, 2j+1
    float add = g_ad2[d];
    float w0 = lrelu_exp(g_as2[d] + add);
    float den = w0;
    float2 acc;
    {
        float2 hv = __half22float2(
            reinterpret_cast<const __half2*>(g_h2 + (size_t)d * OUT2)[j]);
        acc.x = w0 * hv.x; acc.y = w0 * hv.y;
    }
    const int pB = g_off[d], pE = g_off[d + 1];
    for (int p0 = pB; p0 < pE; p0 += 64) {
        int np = min(64, pE - p0);
        __syncthreads();
        if (j < np) {
            int s = g_csrc[p0 + j];
            ssrc[j] = s;
            sw[j] = lrelu_exp(g_as2[s] + add);
        }
        __syncthreads();
        #pragma unroll 4
        for (int e = 0; e < np; e++) {
            int s = ssrc[e];
            float wp = sw[e];
            den += wp;
            float2 hv = __half22float2(
                reinterpret_cast<const __half2*>(g_h2 + (size_t)s * OUT2)[j]);
            acc.x += wp * hv.x; acc.y += wp * hv.y;
        }
    }
    float2 bb = *reinterpret_cast<const float2*>(b2 + 2 * j);
    *reinterpret_cast<float2*>(out + (size_t)d * OUT2 + 2 * j) =
        make_float2(acc.x / den + bb.x, acc.y / den + bb.y);
}

extern "C" void kernel_launch(void* const* d_in, const int* in_sizes, int n_in,
                              void* d_out, int out_size) {
    const float* x    = (const float*)d_in[0];
    const void*  ei   = d_in[1];
    const float* W1   = (const float*)d_in[2];
    const float* as1  = (const float*)d_in[3];
    const float* ad1  = (const float*)d_in[4];
    const float* b1   = (const float*)d_in[5];
    const float* W2   = (const float*)d_in[6];
    const float* as2  = (const float*)d_in[7];
    const float* ad2  = (const float*)d_in[8];
    const float* b2   = (const float*)d_in[9];
    float* out = (float*)d_out;

    const int n_nodes = in_sizes[0] / NF;
    const int E  = in_sizes[1] / 2;

    const int eb = (E + 255) / 256;
    const int nb = (n_nodes + 1023) / 1024;

    static int smem_set = 0;
    if (!smem_set) {
        cudaFuncSetAttribute(k1_gemm1, cudaFuncAttributeMaxDynamicSharedMemorySize, K1_SMEM);
        cudaFuncSetAttribute(k4_gemm2, cudaFuncAttributeMaxDynamicSharedMemorySize, K4_SMEM);
        smem_set = 1;
    }

    dim3 g1((n_nodes + 63) / 64, HH / 64);      // 782 x 4
    dim3 g4((n_nodes + 63) / 64, OUT2 / 64);    // 782 x 2

    kz<<<nb + 1, 1024>>>((const int*)ei, E, n_nodes);          // 1
    kc2_count<<<eb, 256>>>(ei, E);                             // 2
    kv<<<6, 256>>>(W1, as1, ad1, W2, as2, ad2);                // 3
    k1_gemm1<<<g1, 128, K1_SMEM>>>(x, W1, n_nodes);            // 4  <- profiled slot
    s1_scan<<<nb, 1024>>>(n_nodes);                            // 5
    s2_scan<<<1, 32>>>(nb);                                    // 6
    s3_scan<<<nb, 1024>>>(n_nodes, E);                         // 7
    kc3w1<<<eb, 256>>>(ei, E);                                 // 8
    ka1<<<n_nodes, 128>>>(n_nodes);                            // 9
    k4_gemm2<<<g4, 128, K4_SMEM>>>(W2, b1, n_nodes);           // 10
    ka2<<<n_nodes, 64>>>(n_nodes, b2, out);                    // 11
}

// round 14
// speedup vs baseline: 1.7644x; 1.0496x over previous
#include <cuda_runtime.h>
#include <cuda_bf16.h>
#include <cuda_fp16.h>

#define NMAX   50016
#define EMAX   800000
#define NF     128
#define HH     256
#define OUT2   128
#define NHEADS 4
#define NEG    0.2f

// ---- scratch ----
__device__ __half g_h1[(size_t)NMAX * HH];     // fp16 layer-1 features
__device__ __half g_agg1h[(size_t)NMAX * HH];  // fp16 aggregated layer-1
__device__ __half g_h2[(size_t)NMAX * OUT2];   // fp16 layer-2 features
__device__ float g_as1[NMAX * NHEADS];
__device__ float g_ad1[NMAX * NHEADS];
__device__ float g_as2[NMAX];
__device__ float g_ad2[NMAX];
__device__ float g_va1[NF * 8];
__device__ float g_wa2[HH * 2];
__device__ int   g_is64;
// CSR
__device__ int   g_cnt [NMAX + 1];
__device__ int   g_off [NMAX + 1];
__device__ int   g_cur [NMAX + 1];
__device__ int   g_bsum[64];
__device__ int   g_boff[64];
__device__ int   g_csrc[EMAX];
__device__ float g_w1  [(size_t)EMAX * NHEADS];

__device__ __forceinline__ void load_edge(const void* ei, int E, int i,
                                          int& s, int& d) {
    if (g_is64) {
        const long long* p = (const long long*)ei;
        s = (int)p[i]; d = (int)p[(size_t)E + i];
    } else {
        const int* p = (const int*)ei;
        s = p[i]; d = p[E + i];
    }
}

__device__ __forceinline__ float lrelu_exp(float v) {
    v = v > 0.f ? v : NEG * v;
    return __expf(v);
}

#define MMA_BF16(c0,c1,c2,c3,a0,a1,a2,a3,b0,b1) \
    asm("mma.sync.aligned.m16n8k16.row.col.f32.bf16.bf16.f32 " \
        "{%0,%1,%2,%3}, {%4,%5,%6,%7}, {%8,%9}, {%0,%1,%2,%3};" \
        : "+f"(c0), "+f"(c1), "+f"(c2), "+f"(c3) \
        : "r"(a0), "r"(a1), "r"(a2), "r"(a3), "r"(b0), "r"(b1))

#define LDSM4(R0,R1,R2,R3,A) \
    asm volatile("ldmatrix.sync.aligned.m8n8.x4.shared.b16 {%0,%1,%2,%3}, [%4];" \
        : "=r"(R0), "=r"(R1), "=r"(R2), "=r"(R3) : "r"(A))
#define LDSM2T(R0,R1,A) \
    asm volatile("ldmatrix.sync.aligned.m8n8.x2.trans.shared.b16 {%0,%1}, [%2];" \
        : "=r"(R0), "=r"(R1) : "r"(A))

__device__ __forceinline__ unsigned sm_u32(const void* p) {
    return (unsigned)__cvta_generic_to_shared(p);
}

__device__ __forceinline__ unsigned bf16_hi_pack(float a, float b) {
    unsigned ua = (unsigned)__bfloat16_as_ushort(__float2bfloat16(a));
    unsigned ub = (unsigned)__bfloat16_as_ushort(__float2bfloat16(b));
    return ua | (ub << 16);
}
__device__ __forceinline__ unsigned bf16_lo_pack(float a, float b) {
    float ra = a - __bfloat162float(__float2bfloat16(a));
    float rb = b - __bfloat162float(__float2bfloat16(b));
    return bf16_hi_pack(ra, rb);
}

// ============ KZ: dtype probe + zero counts ============
__global__ void kz(const int* ei32, int E, int n) {
    int i = blockIdx.x * 1024 + threadIdx.x;
    if (i <= n) g_cnt[i] = 0;
    if (blockIdx.x == 0) {
        __shared__ int flag;
        if (threadIdx.x == 0) flag = 0;
        __syncthreads();
        for (int j = threadIdx.x; j < 2048; j += 1024) {
            int idx = 2 * j + 1;
            if (idx < 2 * E && ei32[idx] != 0) flag = 1;
        }
        __syncthreads();
        if (threadIdx.x == 0) g_is64 = (flag == 0);
    }
}

// ============ KC2: count in-degrees ============
__global__ void kc2_count(const void* __restrict__ ei, int E) {
    int i = blockIdx.x * blockDim.x + threadIdx.x;
    if (i >= E) return;
    int s, d; load_edge(ei, E, i, s, d);
    atomicAdd(&g_cnt[d], 1);
}

// ============ KV: attention-vector precomputes ============
__global__ void kv(const float* __restrict__ W1, const float* __restrict__ a_s1,
                   const float* __restrict__ a_d1, const float* __restrict__ W2,
                   const float* __restrict__ a_s2, const float* __restrict__ a_d2) {
    int t = blockIdx.x * 256 + threadIdx.x;
    if (t < NF * 8) {
        int k = t >> 3, o = t & 7, h = o & 3;
        const float* a = (o < 4 ? a_s1 : a_d1) + h * 64;
        const float* w = W1 + (size_t)k * HH + h * 64;
        float s = 0.f;
        #pragma unroll 8
        for (int c = 0; c < 64; c++) s += w[c] * a[c];
        g_va1[t] = s;
    } else if (t < NF * 8 + HH * 2) {
        int q = t - NF * 8;
        int k = q >> 1, o = q & 1;
        const float* a = o ? a_d2 : a_s2;
        const float* w = W2 + (size_t)k * OUT2;
        float s = 0.f;
        #pragma unroll 8
        for (int c = 0; c < OUT2; c++) s += w[c] * a[c];
        g_wa2[q] = s;
    }
}

// ==== shared GEMM chunk geometry: 64 rows x 64 cols x 64-k chunks ====
#define CH_PAD  72
#define CH_SZ   (64 * CH_PAD)

// ============ K1: h1 = x @ W1  (chunked bf16-split MMA) + logits ============
#define K1_SMEM (4 * CH_SZ * 2 + NF * 8 * 4)     // 36864 + 4096
__global__ void __launch_bounds__(128, 5)
k1_gemm1(const float* __restrict__ x, const float* __restrict__ W1,
         int n_nodes) {
    extern __shared__ __nv_bfloat16 smb[];
    __nv_bfloat16* Xhi = smb;
    __nv_bfloat16* Xlo = smb + CH_SZ;
    __nv_bfloat16* Whi = smb + 2 * CH_SZ;
    __nv_bfloat16* Wlo = smb + 3 * CH_SZ;
    float* sva = reinterpret_cast<float*>(smb + 4 * CH_SZ);
    const int n0 = blockIdx.x * 64;
    const int c0 = blockIdx.y * 64;
    const int tid = threadIdx.x;                    // 128
    const bool do_logits = (blockIdx.y == 0);
    if (do_logits) for (int i = tid; i < NF * 8; i += 128) sva[i] = g_va1[i];

    const int wid = tid >> 5, lane = tid & 31;
    const int wr = (wid & 1) * 32;
    const int wc = (wid >> 1) * 32;
    const int gq = lane >> 2, tg = lane & 3;

    unsigned aAhi[2], aAlo[2];
    {
        const int ak = (lane >> 4) * 8;
        #pragma unroll
        for (int rg = 0; rg < 2; rg++) {
            int row = wr + rg * 16 + (lane & 15);
            aAhi[rg] = sm_u32(Xhi + row * CH_PAD + ak);
            aAlo[rg] = sm_u32(Xlo + row * CH_PAD + ak);
        }
    }
    unsigned aBhi = sm_u32(Whi + (lane & 15) * CH_PAD + wc);
    unsigned aBlo = sm_u32(Wlo + (lane & 15) * CH_PAD + wc);

    float C[2][4][4] = {};
    float s0 = 0.f, s1 = 0.f, s2 = 0.f, s3 = 0.f;   // logits accum
    #pragma unroll
    for (int kc = 0; kc < 2; kc++) {
        const int kbase = kc * 64;
        __syncthreads();
        // stage X chunk (64 rows x 64 k)
        #pragma unroll
        for (int r = 0; r < 8; r++) {
            int i = tid + r * 128;
            int nn = i >> 4, k4 = i & 15;
            int g = n0 + nn;
            float4 v = make_float4(0.f, 0.f, 0.f, 0.f);
            if (g < n_nodes)
                v = *reinterpret_cast<const float4*>(x + (size_t)g * NF + kbase + 4 * k4);
            uint2 hp, lp;
            hp.x = bf16_hi_pack(v.x, v.y); hp.y = bf16_hi_pack(v.z, v.w);
            lp.x = bf16_lo_pack(v.x, v.y); lp.y = bf16_lo_pack(v.z, v.w);
            *reinterpret_cast<uint2*>(&Xhi[nn * CH_PAD + 4 * k4]) = hp;
            *reinterpret_cast<uint2*>(&Xlo[nn * CH_PAD + 4 * k4]) = lp;
        }
        // stage W chunk (64 k x 64 cols), k-major
        #pragma unroll
        for (int r = 0; r < 8; r++) {
            int i = tid + r * 128;
            int k = i >> 4, c4 = i & 15;
            float4 w = *reinterpret_cast<const float4*>(
                W1 + (size_t)(kbase + k) * HH + c0 + 4 * c4);
            uint2 hp, lp;
            hp.x = bf16_hi_pack(w.x, w.y); hp.y = bf16_hi_pack(w.z, w.w);
            lp.x = bf16_lo_pack(w.x, w.y); lp.y = bf16_lo_pack(w.z, w.w);
            *reinterpret_cast<uint2*>(&Whi[k * CH_PAD + 4 * c4]) = hp;
            *reinterpret_cast<uint2*>(&Wlo[k * CH_PAD + 4 * c4]) = lp;
        }
        __syncthreads();
        // fused layer-1 logits partial (64 nodes x 2 quads)
        if (do_logits) {
            int nn = tid >> 1, o4 = (tid & 1) * 4;
            #pragma unroll 8
            for (int k = 0; k < 64; k++) {
                float xv = __bfloat162float(Xhi[nn * CH_PAD + k]) +
                           __bfloat162float(Xlo[nn * CH_PAD + k]);
                const float* sv = sva + (kbase + k) * 8 + o4;
                s0 += xv * sv[0]; s1 += xv * sv[1];
                s2 += xv * sv[2]; s3 += xv * sv[3];
            }
        }
        // MMA over chunk (4 k16 steps)
        #pragma unroll
        for (int ks = 0; ks < 4; ks++) {
            const unsigned koffA = ks * 32;
            const unsigned koffB = ks * 16 * CH_PAD * 2;
            unsigned ah[2][4], al[2][4];
            #pragma unroll
            for (int rg = 0; rg < 2; rg++) {
                LDSM4(ah[rg][0], ah[rg][1], ah[rg][2], ah[rg][3], aAhi[rg] + koffA);
                LDSM4(al[rg][0], al[rg][1], al[rg][2], al[rg][3], aAlo[rg] + koffA);
            }
            #pragma unroll
            for (int ns = 0; ns < 4; ns++) {
                unsigned bh0, bh1, bl0, bl1;
                LDSM2T(bh0, bh1, aBhi + koffB + ns * 16);
                LDSM2T(bl0, bl1, aBlo + koffB + ns * 16);
                #pragma unroll
                for (int rg = 0; rg < 2; rg++) {
                    MMA_BF16(C[rg][ns][0], C[rg][ns][1], C[rg][ns][2], C[rg][ns][3],
                             ah[rg][0], ah[rg][1], ah[rg][2], ah[rg][3], bh0, bh1);
                    MMA_BF16(C[rg][ns][0], C[rg][ns][1], C[rg][ns][2], C[rg][ns][3],
                             ah[rg][0], ah[rg][1], ah[rg][2], ah[rg][3], bl0, bl1);
                    MMA_BF16(C[rg][ns][0], C[rg][ns][1], C[rg][ns][2], C[rg][ns][3],
                             al[rg][0], al[rg][1], al[rg][2], al[rg][3], bh0, bh1);
                }
            }
        }
    }
    #pragma unroll
    for (int rg = 0; rg < 2; rg++) {
        #pragma unroll
        for (int ns = 0; ns < 4; ns++) {
            int col = c0 + wc + ns * 8 + 2 * tg;
            int r0 = n0 + wr + rg * 16 + gq;
            if (r0 < n_nodes)
                *reinterpret_cast<__half2*>(g_h1 + (size_t)r0 * HH + col) =
                    __floats2half2_rn(C[rg][ns][0], C[rg][ns][1]);
            if (r0 + 8 < n_nodes)
                *reinterpret_cast<__half2*>(g_h1 + (size_t)(r0 + 8) * HH + col) =
                    __floats2half2_rn(C[rg][ns][2], C[rg][ns][3]);
        }
    }
    if (do_logits) {
        int nn = tid >> 1, o4 = (tid & 1) * 4;
        int g = n0 + nn;
        if (g < n_nodes) {
            float* dst = (o4 == 0 ? g_as1 : g_ad1) + g * 4;
            *reinterpret_cast<float4*>(dst) = make_float4(s0, s1, s2, s3);
        }
    }
}

// ============ scan ============
__global__ void s1_scan(int n) {
    __shared__ int sd[1024];
    int tid = threadIdx.x;
    int i = blockIdx.x * 1024 + tid;
    int v = (i < n) ? g_cnt[i] : 0;
    sd[tid] = v;
    __syncthreads();
    #pragma unroll
    for (int off = 1; off < 1024; off <<= 1) {
        int t = (tid >= off) ? sd[tid - off] : 0;
        __syncthreads();
        sd[tid] += t;
        __syncthreads();
    }
    if (i < n) g_off[i] = sd[tid] - v;
    if (tid == 1023) g_bsum[blockIdx.x] = sd[1023];
}
__global__ void s2_scan(int nb) {
    if (threadIdx.x == 0) {
        int acc = 0;
        for (int b = 0; b < nb; b++) { int t = g_bsum[b]; g_boff[b] = acc; acc += t; }
    }
}
__global__ void s3_scan(int n, int E) {
    int i = blockIdx.x * 1024 + threadIdx.x;
    if (i < n) {
        int v = g_off[i] + g_boff[blockIdx.x];
        g_off[i] = v;
        g_cur[i] = v;
    }
    if (i == 0) g_off[n] = E;
}

// ============ KC3W1: CSR fill + layer-1 softmax numerators ============
__global__ void kc3w1(const void* __restrict__ ei, int E) {
    int i = blockIdx.x * blockDim.x + threadIdx.x;
    if (i >= E) return;
    int s, d; load_edge(ei, E, i, s, d);
    int p = atomicAdd(&g_cur[d], 1);
    g_csrc[p] = s;
    float4 as = *reinterpret_cast<const float4*>(g_as1 + 4 * s);
    float4 ad = *reinterpret_cast<const float4*>(g_ad1 + 4 * d);
    float4 w;
    w.x = lrelu_exp(as.x + ad.x);
    w.y = lrelu_exp(as.y + ad.y);
    w.z = lrelu_exp(as.z + ad.z);
    w.w = lrelu_exp(as.w + ad.w);
    *reinterpret_cast<float4*>(g_w1 + (size_t)p * 4) = w;
}

// ============ KA1: gather aggregation, layer 1 (fp16 in, fp16 out) ==========
__global__ void ka1(int n_nodes) {
    __shared__ int   ssrc[128];
    __shared__ float sw[128 * 4];
    const int d = blockIdx.x;
    const int j = threadIdx.x;        // 128: features 2j, 2j+1
    const int h = j >> 5;             // head of feature 2j
    float w0 = lrelu_exp(g_as1[d * NHEADS + h] + g_ad1[d * NHEADS + h]);
    float den = w0;
    float2 acc;
    {
        float2 hv = __half22float2(
            reinterpret_cast<const __half2*>(g_h1 + (size_t)d * HH)[j]);
        acc.x = w0 * hv.x; acc.y = w0 * hv.y;
    }
    const int pB = g_off[d], pE = g_off[d + 1];
    for (int p0 = pB; p0 < pE; p0 += 128) {
        int np = min(128, pE - p0);
        __syncthreads();
        if (j < np) {
            ssrc[j] = g_csrc[p0 + j];
            *reinterpret_cast<float4*>(&sw[4 * j]) =
                *reinterpret_cast<const float4*>(g_w1 + (size_t)(p0 + j) * 4);
        }
        __syncthreads();
        #pragma unroll 8
        for (int e = 0; e < np; e++) {
            int s = ssrc[e];
            float wp = sw[4 * e + h];
            den += wp;
            float2 hv = __half22float2(
                reinterpret_cast<const __half2*>(g_h1 + (size_t)s * HH)[j]);
            acc.x += wp * hv.x; acc.y += wp * hv.y;
        }
    }
    reinterpret_cast<__half2*>(g_agg1h + (size_t)d * HH)[j] =
        __floats2half2_rn(acc.x / den, acc.y / den);
}

// ============ K4: h2 = elu(agg1+b1) @ W2 (chunked MMA) + layer-2 logits =====
#define K4_SMEM (4 * CH_SZ * 2 + HH * 2 * 4)     // 36864 + 2048
__global__ void __launch_bounds__(128, 5)
k4_gemm2(const float* __restrict__ W2, const float* __restrict__ b1,
         int n_nodes) {
    extern __shared__ __nv_bfloat16 smb[];
    __nv_bfloat16* Xhi = smb;
    __nv_bfloat16* Xlo = smb + CH_SZ;
    __nv_bfloat16* Whi = smb + 2 * CH_SZ;
    __nv_bfloat16* Wlo = smb + 3 * CH_SZ;
    float* swa = reinterpret_cast<float*>(smb + 4 * CH_SZ);
    const int n0 = blockIdx.x * 64;
    const int c0 = blockIdx.y * 64;
    const int tid = threadIdx.x;      // 128
    const bool do_logits = (blockIdx.y == 0);
    if (do_logits) for (int i = tid; i < HH * 2; i += 128) swa[i] = g_wa2[i];

    const int wid = tid >> 5, lane = tid & 31;
    const int wr = (wid & 1) * 32;
    const int wc = (wid >> 1) * 32;
    const int gq = lane >> 2, tg = lane & 3;

    unsigned aAhi[2], aAlo[2];
    {
        const int ak = (lane >> 4) * 8;
        #pragma unroll
        for (int rg = 0; rg < 2; rg++) {
            int row = wr + rg * 16 + (lane & 15);
            aAhi[rg] = sm_u32(Xhi + row * CH_PAD + ak);
            aAlo[rg] = sm_u32(Xlo + row * CH_PAD + ak);
        }
    }
    unsigned aBhi = sm_u32(Whi + (lane & 15) * CH_PAD + wc);
    unsigned aBlo = sm_u32(Wlo + (lane & 15) * CH_PAD + wc);

    float C[2][4][4] = {};
    float ls = 0.f;
    #pragma unroll
    for (int kc = 0; kc < 4; kc++) {
        const int kbase = kc * 64;
        __syncthreads();
        // stage X chunk: elu(agg1h + b1), hi/lo split
        #pragma unroll
        for (int r = 0; r < 8; r++) {
            int i = tid + r * 128;
            int nn = i >> 4, k4 = i & 15;
            int g = n0 + nn;
            float4 v = make_float4(0.f, 0.f, 0.f, 0.f);
            if (g < n_nodes) {
                int kk = kbase + 4 * k4;
                uint2 raw = *reinterpret_cast<const uint2*>(g_agg1h + (size_t)g * HH + kk);
                float2 f01 = __half22float2(*reinterpret_cast<__half2*>(&raw.x));
                float2 f23 = __half22float2(*reinterpret_cast<__half2*>(&raw.y));
                float4 b = *reinterpret_cast<const float4*>(b1 + kk);
                v.x = f01.x + b.x; v.y = f01.y + b.y;
                v.z = f23.x + b.z; v.w = f23.y + b.w;
                v.x = v.x > 0.f ? v.x : expm1f(v.x);
                v.y = v.y > 0.f ? v.y : expm1f(v.y);
                v.z = v.z > 0.f ? v.z : expm1f(v.z);
                v.w = v.w > 0.f ? v.w : expm1f(v.w);
            }
            uint2 hp, lp;
            hp.x = bf16_hi_pack(v.x, v.y); hp.y = bf16_hi_pack(v.z, v.w);
            lp.x = bf16_lo_pack(v.x, v.y); lp.y = bf16_lo_pack(v.z, v.w);
            *reinterpret_cast<uint2*>(&Xhi[nn * CH_PAD + 4 * k4]) = hp;
            *reinterpret_cast<uint2*>(&Xlo[nn * CH_PAD + 4 * k4]) = lp;
        }
        // stage W chunk k-major
        #pragma unroll
        for (int r = 0; r < 8; r++) {
            int i = tid + r * 128;
            int k = i >> 4, c4 = i & 15;
            float4 w = *reinterpret_cast<const float4*>(
                W2 + (size_t)(kbase + k) * OUT2 + c0 + 4 * c4);
            uint2 hp, lp;
            hp.x = bf16_hi_pack(w.x, w.y); hp.y = bf16_hi_pack(w.z, w.w);
            lp.x = bf16_lo_pack(w.x, w.y); lp.y = bf16_lo_pack(w.z, w.w);
            *reinterpret_cast<uint2*>(&Whi[k * CH_PAD + 4 * c4]) = hp;
            *reinterpret_cast<uint2*>(&Wlo[k * CH_PAD + 4 * c4]) = lp;
        }
        __syncthreads();
        if (do_logits) {
            int nn = tid >> 1, o = tid & 1;
            #pragma unroll 8
            for (int k = 0; k < 64; k++) {
                float xvv = __bfloat162float(Xhi[nn * CH_PAD + k]) +
                            __bfloat162float(Xlo[nn * CH_PAD + k]);
                ls += xvv * swa[2 * (kbase + k) + o];
            }
        }
        #pragma unroll
        for (int ks = 0; ks < 4; ks++) {
            const unsigned koffA = ks * 32;
            const unsigned koffB = ks * 16 * CH_PAD * 2;
            unsigned ah[2][4], al[2][4];
            #pragma unroll
            for (int rg = 0; rg < 2; rg++) {
                LDSM4(ah[rg][0], ah[rg][1], ah[rg][2], ah[rg][3], aAhi[rg] + koffA);
                LDSM4(al[rg][0], al[rg][1], al[rg][2], al[rg][3], aAlo[rg] + koffA);
            }
            #pragma unroll
            for (int ns = 0; ns < 4; ns++) {
                unsigned bh0, bh1, bl0, bl1;
                LDSM2T(bh0, bh1, aBhi + koffB + ns * 16);
                LDSM2T(bl0, bl1, aBlo + koffB + ns * 16);
                #pragma unroll
                for (int rg = 0; rg < 2; rg++) {
                    MMA_BF16(C[rg][ns][0], C[rg][ns][1], C[rg][ns][2], C[rg][ns][3],
                             ah[rg][0], ah[rg][1], ah[rg][2], ah[rg][3], bh0, bh1);
                    MMA_BF16(C[rg][ns][0], C[rg][ns][1], C[rg][ns][2], C[rg][ns][3],
                             ah[rg][0], ah[rg][1], ah[rg][2], ah[rg][3], bl0, bl1);
                    MMA_BF16(C[rg][ns][0], C[rg][ns][1], C[rg][ns][2], C[rg][ns][3],
                             al[rg][0], al[rg][1], al[rg][2], al[rg][3], bh0, bh1);
                }
            }
        }
    }
    #pragma unroll
    for (int rg = 0; rg < 2; rg++) {
        #pragma unroll
        for (int ns = 0; ns < 4; ns++) {
            int col = c0 + wc + ns * 8 + 2 * tg;
            int r0 = n0 + wr + rg * 16 + gq;
            if (r0 < n_nodes)
                *reinterpret_cast<__half2*>(g_h2 + (size_t)r0 * OUT2 + col) =
                    __floats2half2_rn(C[rg][ns][0], C[rg][ns][1]);
            if (r0 + 8 < n_nodes)
                *reinterpret_cast<__half2*>(g_h2 + (size_t)(r0 + 8) * OUT2 + col) =
                    __floats2half2_rn(C[rg][ns][2], C[rg][ns][3]);
        }
    }
    if (do_logits) {
        int nn = tid >> 1, o = tid & 1;
        int g = n0 + nn;
        if (g < n_nodes) {
            if (o == 0) g_as2[g] = ls;
            else        g_ad2[g] = ls;
        }
    }
}

// ============ KA2: gather aggregation, layer 2 (fp16 rows, 64 thr) ==========
__global__ void ka2(int n_nodes, const float* __restrict__ b2,
                    float* __restrict__ out) {
    __shared__ int   ssrc[64];
    __shared__ float sw[64];
    const int d = blockIdx.x;
    const int j = threadIdx.x;   // 64: features 2j, 2j+1
    float add = g_ad2[d];
    float w0 = lrelu_exp(g_as2[d] + add);
    float den = w0;
    float2 acc;
    {
        float2 hv = __half22float2(
            reinterpret_cast<const __half2*>(g_h2 + (size_t)d * OUT2)[j]);
        acc.x = w0 * hv.x; acc.y = w0 * hv.y;
    }
    const int pB = g_off[d], pE = g_off[d + 1];
    for (int p0 = pB; p0 < pE; p0 += 64) {
        int np = min(64, pE - p0);
        __syncthreads();
        if (j < np) {
            int s = g_csrc[p0 + j];
            ssrc[j] = s;
            sw[j] = lrelu_exp(g_as2[s] + add);
        }
        __syncthreads();
        #pragma unroll 8
        for (int e = 0; e < np; e++) {
            int s = ssrc[e];
            float wp = sw[e];
            den += wp;
            float2 hv = __half22float2(
                reinterpret_cast<const __half2*>(g_h2 + (size_t)s * OUT2)[j]);
            acc.x += wp * hv.x; acc.y += wp * hv.y;
        }
    }
    float2 bb = *reinterpret_cast<const float2*>(b2 + 2 * j);
    *reinterpret_cast<float2*>(out + (size_t)d * OUT2 + 2 * j) =
        make_float2(acc.x / den + bb.x, acc.y / den + bb.y);
}

extern "C" void kernel_launch(void* const* d_in, const int* in_sizes, int n_in,
                              void* d_out, int out_size) {
    const float* x    = (const float*)d_in[0];
    const void*  ei   = d_in[1];
    const float* W1   = (const float*)d_in[2];
    const float* as1  = (const float*)d_in[3];
    const float* ad1  = (const float*)d_in[4];
    const float* b1   = (const float*)d_in[5];
    const float* W2   = (const float*)d_in[6];
    const float* as2  = (const float*)d_in[7];
    const float* ad2  = (const float*)d_in[8];
    const float* b2   = (const float*)d_in[9];
    float* out = (float*)d_out;

    const int n_nodes = in_sizes[0] / NF;
    const int E  = in_sizes[1] / 2;

    const int eb = (E + 255) / 256;
    const int nb = (n_nodes + 1023) / 1024;

    static int smem_set = 0;
    if (!smem_set) {
        cudaFuncSetAttribute(k1_gemm1, cudaFuncAttributeMaxDynamicSharedMemorySize, K1_SMEM);
        cudaFuncSetAttribute(k4_gemm2, cudaFuncAttributeMaxDynamicSharedMemorySize, K4_SMEM);
        smem_set = 1;
    }

    dim3 g1((n_nodes + 63) / 64, HH / 64);      // 782 x 4
    dim3 g4((n_nodes + 63) / 64, OUT2 / 64);    // 782 x 2

    kz<<<nb + 1, 1024>>>((const int*)ei, E, n_nodes);          // 1
    kc2_count<<<eb, 256>>>(ei, E);                             // 2
    kv<<<6, 256>>>(W1, as1, ad1, W2, as2, ad2);                // 3
    k1_gemm1<<<g1, 128, K1_SMEM>>>(x, W1, n_nodes);            // 4  <- profiled slot
    s1_scan<<<nb, 1024>>>(n_nodes);                            // 5
    s2_scan<<<1, 32>>>(nb);                                    // 6
    s3_scan<<<nb, 1024>>>(n_nodes, E);                         // 7
    kc3w1<<<eb, 256>>>(ei, E);                                 // 8
    ka1<<<n_nodes, 128>>>(n_nodes);                            // 9
    k4_gemm2<<<g4, 128, K4_SMEM>>>(W2, b1, n_nodes);           // 10
    ka2<<<n_nodes, 64>>>(n_nodes, b2, out);                    // 11
}

// round 15
// speedup vs baseline: 1.8155x; 1.0290x over previous
#include <cuda_runtime.h>
#include <cuda_bf16.h>
#include <cuda_fp16.h>

#define NMAX   50016
#define EMAX   800000
#define NF     128
#define HH     256
#define OUT2   128
#define NHEADS 4
#define NEG    0.2f

// ---- scratch ----
__device__ __half g_h1[(size_t)NMAX * HH];     // fp16 layer-1 features
__device__ __half g_agg1h[(size_t)NMAX * HH];  // fp16 aggregated layer-1
__device__ __half g_h2[(size_t)NMAX * OUT2];   // fp16 layer-2 features
__device__ float g_as1[NMAX * NHEADS];
__device__ float g_ad1[NMAX * NHEADS];
__device__ float g_as2[NMAX];
__device__ float g_ad2[NMAX];
__device__ float g_va1[NF * 8];
__device__ float g_wa2[HH * 2];
__device__ int   g_is64;
// CSR
__device__ int   g_cnt [NMAX + 1];
__device__ int   g_off [NMAX + 1];
__device__ int   g_cur [NMAX + 1];
__device__ int   g_bsum[64];
__device__ int   g_boff[64];
__device__ int   g_csrc[EMAX];

__device__ __forceinline__ void load_edge(const void* ei, int E, int i,
                                          int& s, int& d) {
    if (g_is64) {
        const long long* p = (const long long*)ei;
        s = (int)p[i]; d = (int)p[(size_t)E + i];
    } else {
        const int* p = (const int*)ei;
        s = p[i]; d = p[E + i];
    }
}

__device__ __forceinline__ float lrelu_exp(float v) {
    v = v > 0.f ? v : NEG * v;
    return __expf(v);
}

#define MMA_BF16(c0,c1,c2,c3,a0,a1,a2,a3,b0,b1) \
    asm("mma.sync.aligned.m16n8k16.row.col.f32.bf16.bf16.f32 " \
        "{%0,%1,%2,%3}, {%4,%5,%6,%7}, {%8,%9}, {%0,%1,%2,%3};" \
        : "+f"(c0), "+f"(c1), "+f"(c2), "+f"(c3) \
        : "r"(a0), "r"(a1), "r"(a2), "r"(a3), "r"(b0), "r"(b1))

#define LDSM4(R0,R1,R2,R3,A) \
    asm volatile("ldmatrix.sync.aligned.m8n8.x4.shared.b16 {%0,%1,%2,%3}, [%4];" \
        : "=r"(R0), "=r"(R1), "=r"(R2), "=r"(R3) : "r"(A))
#define LDSM2T(R0,R1,A) \
    asm volatile("ldmatrix.sync.aligned.m8n8.x2.trans.shared.b16 {%0,%1}, [%2];" \
        : "=r"(R0), "=r"(R1) : "r"(A))

__device__ __forceinline__ unsigned sm_u32(const void* p) {
    return (unsigned)__cvta_generic_to_shared(p);
}

__device__ __forceinline__ unsigned bf16_hi_pack(float a, float b) {
    unsigned ua = (unsigned)__bfloat16_as_ushort(__float2bfloat16(a));
    unsigned ub = (unsigned)__bfloat16_as_ushort(__float2bfloat16(b));
    return ua | (ub << 16);
}
__device__ __forceinline__ unsigned bf16_lo_pack(float a, float b) {
    float ra = a - __bfloat162float(__float2bfloat16(a));
    float rb = b - __bfloat162float(__float2bfloat16(b));
    return bf16_hi_pack(ra, rb);
}

// ============ KZ: dtype probe + zero counts ============
__global__ void kz(const int* ei32, int E, int n) {
    int i = blockIdx.x * 1024 + threadIdx.x;
    if (i <= n) g_cnt[i] = 0;
    if (blockIdx.x == 0) {
        __shared__ int flag;
        if (threadIdx.x == 0) flag = 0;
        __syncthreads();
        for (int j = threadIdx.x; j < 2048; j += 1024) {
            int idx = 2 * j + 1;
            if (idx < 2 * E && ei32[idx] != 0) flag = 1;
        }
        __syncthreads();
        if (threadIdx.x == 0) g_is64 = (flag == 0);
    }
}

// ============ KC2: count in-degrees ============
__global__ void kc2_count(const void* __restrict__ ei, int E) {
    int i = blockIdx.x * blockDim.x + threadIdx.x;
    if (i >= E) return;
    int s, d; load_edge(ei, E, i, s, d);
    atomicAdd(&g_cnt[d], 1);
}

// ============ KV: attention-vector precomputes ============
__global__ void kv(const float* __restrict__ W1, const float* __restrict__ a_s1,
                   const float* __restrict__ a_d1, const float* __restrict__ W2,
                   const float* __restrict__ a_s2, const float* __restrict__ a_d2) {
    int t = blockIdx.x * 256 + threadIdx.x;
    if (t < NF * 8) {
        int k = t >> 3, o = t & 7, h = o & 3;
        const float* a = (o < 4 ? a_s1 : a_d1) + h * 64;
        const float* w = W1 + (size_t)k * HH + h * 64;
        float s = 0.f;
        #pragma unroll 8
        for (int c = 0; c < 64; c++) s += w[c] * a[c];
        g_va1[t] = s;
    } else if (t < NF * 8 + HH * 2) {
        int q = t - NF * 8;
        int k = q >> 1, o = q & 1;
        const float* a = o ? a_d2 : a_s2;
        const float* w = W2 + (size_t)k * OUT2;
        float s = 0.f;
        #pragma unroll 8
        for (int c = 0; c < OUT2; c++) s += w[c] * a[c];
        g_wa2[q] = s;
    }
}

// ==== shared GEMM chunk geometry: 64 rows x 64 cols x 64-k chunks ====
#define CH_PAD  72
#define CH_SZ   (64 * CH_PAD)

// ============ K1: h1 = x @ W1  (chunked bf16-split MMA) + logits ============
#define K1_SMEM (4 * CH_SZ * 2 + NF * 8 * 4)
__global__ void __launch_bounds__(128, 5)
k1_gemm1(const float* __restrict__ x, const float* __restrict__ W1,
         int n_nodes) {
    extern __shared__ __nv_bfloat16 smb[];
    __nv_bfloat16* Xhi = smb;
    __nv_bfloat16* Xlo = smb + CH_SZ;
    __nv_bfloat16* Whi = smb + 2 * CH_SZ;
    __nv_bfloat16* Wlo = smb + 3 * CH_SZ;
    float* sva = reinterpret_cast<float*>(smb + 4 * CH_SZ);
    const int n0 = blockIdx.x * 64;
    const int c0 = blockIdx.y * 64;
    const int tid = threadIdx.x;                    // 128
    const bool do_logits = (blockIdx.y == 0);
    if (do_logits) for (int i = tid; i < NF * 8; i += 128) sva[i] = g_va1[i];

    const int wid = tid >> 5, lane = tid & 31;
    const int wr = (wid & 1) * 32;
    const int wc = (wid >> 1) * 32;
    const int gq = lane >> 2, tg = lane & 3;

    unsigned aAhi[2], aAlo[2];
    {
        const int ak = (lane >> 4) * 8;
        #pragma unroll
        for (int rg = 0; rg < 2; rg++) {
            int row = wr + rg * 16 + (lane & 15);
            aAhi[rg] = sm_u32(Xhi + row * CH_PAD + ak);
            aAlo[rg] = sm_u32(Xlo + row * CH_PAD + ak);
        }
    }
    unsigned aBhi = sm_u32(Whi + (lane & 15) * CH_PAD + wc);
    unsigned aBlo = sm_u32(Wlo + (lane & 15) * CH_PAD + wc);

    float C[2][4][4] = {};
    float s0 = 0.f, s1 = 0.f, s2 = 0.f, s3 = 0.f;
    #pragma unroll
    for (int kc = 0; kc < 2; kc++) {
        const int kbase = kc * 64;
        __syncthreads();
        #pragma unroll
        for (int r = 0; r < 8; r++) {
            int i = tid + r * 128;
            int nn = i >> 4, k4 = i & 15;
            int g = n0 + nn;
            float4 v = make_float4(0.f, 0.f, 0.f, 0.f);
            if (g < n_nodes)
                v = *reinterpret_cast<const float4*>(x + (size_t)g * NF + kbase + 4 * k4);
            uint2 hp, lp;
            hp.x = bf16_hi_pack(v.x, v.y); hp.y = bf16_hi_pack(v.z, v.w);
            lp.x = bf16_lo_pack(v.x, v.y); lp.y = bf16_lo_pack(v.z, v.w);
            *reinterpret_cast<uint2*>(&Xhi[nn * CH_PAD + 4 * k4]) = hp;
            *reinterpret_cast<uint2*>(&Xlo[nn * CH_PAD + 4 * k4]) = lp;
        }
        #pragma unroll
        for (int r = 0; r < 8; r++) {
            int i = tid + r * 128;
            int k = i >> 4, c4 = i & 15;
            float4 w = *reinterpret_cast<const float4*>(
                W1 + (size_t)(kbase + k) * HH + c0 + 4 * c4);
            uint2 hp, lp;
            hp.x = bf16_hi_pack(w.x, w.y); hp.y = bf16_hi_pack(w.z, w.w);
            lp.x = bf16_lo_pack(w.x, w.y); lp.y = bf16_lo_pack(w.z, w.w);
            *reinterpret_cast<uint2*>(&Whi[k * CH_PAD + 4 * c4]) = hp;
            *reinterpret_cast<uint2*>(&Wlo[k * CH_PAD + 4 * c4]) = lp;
        }
        __syncthreads();
        if (do_logits) {
            int nn = tid >> 1, o4 = (tid & 1) * 4;
            #pragma unroll 8
            for (int k = 0; k < 64; k++) {
                float xv = __bfloat162float(Xhi[nn * CH_PAD + k]) +
                           __bfloat162float(Xlo[nn * CH_PAD + k]);
                const float* sv = sva + (kbase + k) * 8 + o4;
                s0 += xv * sv[0]; s1 += xv * sv[1];
                s2 += xv * sv[2]; s3 += xv * sv[3];
            }
        }
        #pragma unroll
        for (int ks = 0; ks < 4; ks++) {
            const unsigned koffA = ks * 32;
            const unsigned koffB = ks * 16 * CH_PAD * 2;
            unsigned ah[2][4], al[2][4];
            #pragma unroll
            for (int rg = 0; rg < 2; rg++) {
                LDSM4(ah[rg][0], ah[rg][1], ah[rg][2], ah[rg][3], aAhi[rg] + koffA);
                LDSM4(al[rg][0], al[rg][1], al[rg][2], al[rg][3], aAlo[rg] + koffA);
            }
            #pragma unroll
            for (int ns = 0; ns < 4; ns++) {
                unsigned bh0, bh1, bl0, bl1;
                LDSM2T(bh0, bh1, aBhi + koffB + ns * 16);
                LDSM2T(bl0, bl1, aBlo + koffB + ns * 16);
                #pragma unroll
                for (int rg = 0; rg < 2; rg++) {
                    MMA_BF16(C[rg][ns][0], C[rg][ns][1], C[rg][ns][2], C[rg][ns][3],
                             ah[rg][0], ah[rg][1], ah[rg][2], ah[rg][3], bh0, bh1);
                    MMA_BF16(C[rg][ns][0], C[rg][ns][1], C[rg][ns][2], C[rg][ns][3],
                             ah[rg][0], ah[rg][1], ah[rg][2], ah[rg][3], bl0, bl1);
                    MMA_BF16(C[rg][ns][0], C[rg][ns][1], C[rg][ns][2], C[rg][ns][3],
                             al[rg][0], al[rg][1], al[rg][2], al[rg][3], bh0, bh1);
                }
            }
        }
    }
    #pragma unroll
    for (int rg = 0; rg < 2; rg++) {
        #pragma unroll
        for (int ns = 0; ns < 4; ns++) {
            int col = c0 + wc + ns * 8 + 2 * tg;
            int r0 = n0 + wr + rg * 16 + gq;
            if (r0 < n_nodes)
                *reinterpret_cast<__half2*>(g_h1 + (size_t)r0 * HH + col) =
                    __floats2half2_rn(C[rg][ns][0], C[rg][ns][1]);
            if (r0 + 8 < n_nodes)
                *reinterpret_cast<__half2*>(g_h1 + (size_t)(r0 + 8) * HH + col) =
                    __floats2half2_rn(C[rg][ns][2], C[rg][ns][3]);
        }
    }
    if (do_logits) {
        int nn = tid >> 1, o4 = (tid & 1) * 4;
        int g = n0 + nn;
        if (g < n_nodes) {
            float* dst = (o4 == 0 ? g_as1 : g_ad1) + g * 4;
            *reinterpret_cast<float4*>(dst) = make_float4(s0, s1, s2, s3);
        }
    }
}

// ============ scan ============
__global__ void s1_scan(int n) {
    __shared__ int sd[1024];
    int tid = threadIdx.x;
    int i = blockIdx.x * 1024 + tid;
    int v = (i < n) ? g_cnt[i] : 0;
    sd[tid] = v;
    __syncthreads();
    #pragma unroll
    for (int off = 1; off < 1024; off <<= 1) {
        int t = (tid >= off) ? sd[tid - off] : 0;
        __syncthreads();
        sd[tid] += t;
        __syncthreads();
    }
    if (i < n) g_off[i] = sd[tid] - v;
    if (tid == 1023) g_bsum[blockIdx.x] = sd[1023];
}
__global__ void s2_scan(int nb) {
    if (threadIdx.x == 0) {
        int acc = 0;
        for (int b = 0; b < nb; b++) { int t = g_bsum[b]; g_boff[b] = acc; acc += t; }
    }
}
__global__ void s3_scan(int n, int E) {
    int i = blockIdx.x * 1024 + threadIdx.x;
    if (i < n) {
        int v = g_off[i] + g_boff[blockIdx.x];
        g_off[i] = v;
        g_cur[i] = v;
    }
    if (i == 0) g_off[n] = E;
}

// ============ KC3: CSR fill (src only — weights computed in ka1) ============
__global__ void kc3(const void* __restrict__ ei, int E) {
    int i = blockIdx.x * blockDim.x + threadIdx.x;
    if (i >= E) return;
    int s, d; load_edge(ei, E, i, s, d);
    int p = atomicAdd(&g_cur[d], 1);
    g_csrc[p] = s;
}

// ============ KA1: gather aggregation, layer 1 (inline softmax weights) =====
__global__ void ka1(int n_nodes) {
    __shared__ int   ssrc[128];
    __shared__ float sw[128 * 4];
    const int d = blockIdx.x;
    const int j = threadIdx.x;        // 128: features 2j, 2j+1
    const int h = j >> 5;             // head of feature 2j
    const float4 ad4 = *reinterpret_cast<const float4*>(g_ad1 + 4 * d);
    float adh = (h == 0) ? ad4.x : (h == 1) ? ad4.y : (h == 2) ? ad4.z : ad4.w;
    float w0 = lrelu_exp(g_as1[d * NHEADS + h] + adh);
    float den = w0;
    float2 acc;
    {
        float2 hv = __half22float2(
            reinterpret_cast<const __half2*>(g_h1 + (size_t)d * HH)[j]);
        acc.x = w0 * hv.x; acc.y = w0 * hv.y;
    }
    const int pB = g_off[d], pE = g_off[d + 1];
    for (int p0 = pB; p0 < pE; p0 += 128) {
        int np = min(128, pE - p0);
        __syncthreads();
        if (j < np) {
            int s = g_csrc[p0 + j];
            ssrc[j] = s;
            float4 as = *reinterpret_cast<const float4*>(g_as1 + 4 * s);
            sw[4 * j + 0] = lrelu_exp(as.x + ad4.x);
            sw[4 * j + 1] = lrelu_exp(as.y + ad4.y);
            sw[4 * j + 2] = lrelu_exp(as.z + ad4.z);
            sw[4 * j + 3] = lrelu_exp(as.w + ad4.w);
        }
        __syncthreads();
        #pragma unroll 8
        for (int e = 0; e < np; e++) {
            int s = ssrc[e];
            float wp = sw[4 * e + h];
            den += wp;
            float2 hv = __half22float2(
                reinterpret_cast<const __half2*>(g_h1 + (size_t)s * HH)[j]);
            acc.x += wp * hv.x; acc.y += wp * hv.y;
        }
    }
    reinterpret_cast<__half2*>(g_agg1h + (size_t)d * HH)[j] =
        __floats2half2_rn(acc.x / den, acc.y / den);
}

// ============ K4: h2 = elu(agg1+b1) @ W2 (chunked MMA) + layer-2 logits =====
#define K4_SMEM (4 * CH_SZ * 2 + HH * 2 * 4)
__global__ void __launch_bounds__(128, 5)
k4_gemm2(const float* __restrict__ W2, const float* __restrict__ b1,
         int n_nodes) {
    extern __shared__ __nv_bfloat16 smb[];
    __nv_bfloat16* Xhi = smb;
    __nv_bfloat16* Xlo = smb + CH_SZ;
    __nv_bfloat16* Whi = smb + 2 * CH_SZ;
    __nv_bfloat16* Wlo = smb + 3 * CH_SZ;
    float* swa = reinterpret_cast<float*>(smb + 4 * CH_SZ);
    const int n0 = blockIdx.x * 64;
    const int c0 = blockIdx.y * 64;
    const int tid = threadIdx.x;      // 128
    const bool do_logits = (blockIdx.y == 0);
    if (do_logits) for (int i = tid; i < HH * 2; i += 128) swa[i] = g_wa2[i];

    const int wid = tid >> 5, lane = tid & 31;
    const int wr = (wid & 1) * 32;
    const int wc = (wid >> 1) * 32;
    const int gq = lane >> 2, tg = lane & 3;

    unsigned aAhi[2], aAlo[2];
    {
        const int ak = (lane >> 4) * 8;
        #pragma unroll
        for (int rg = 0; rg < 2; rg++) {
            int row = wr + rg * 16 + (lane & 15);
            aAhi[rg] = sm_u32(Xhi + row * CH_PAD + ak);
            aAlo[rg] = sm_u32(Xlo + row * CH_PAD + ak);
        }
    }
    unsigned aBhi = sm_u32(Whi + (lane & 15) * CH_PAD + wc);
    unsigned aBlo = sm_u32(Wlo + (lane & 15) * CH_PAD + wc);

    float C[2][4][4] = {};
    float ls = 0.f;
    #pragma unroll
    for (int kc = 0; kc < 4; kc++) {
        const int kbase = kc * 64;
        __syncthreads();
        #pragma unroll
        for (int r = 0; r < 8; r++) {
            int i = tid + r * 128;
            int nn = i >> 4, k4 = i & 15;
            int g = n0 + nn;
            float4 v = make_float4(0.f, 0.f, 0.f, 0.f);
            if (g < n_nodes) {
                int kk = kbase + 4 * k4;
                uint2 raw = *reinterpret_cast<const uint2*>(g_agg1h + (size_t)g * HH + kk);
                float2 f01 = __half22float2(*reinterpret_cast<__half2*>(&raw.x));
                float2 f23 = __half22float2(*reinterpret_cast<__half2*>(&raw.y));
                float4 b = *reinterpret_cast<const float4*>(b1 + kk);
                v.x = f01.x + b.x; v.y = f01.y + b.y;
                v.z = f23.x + b.z; v.w = f23.y + b.w;
                v.x = v.x > 0.f ? v.x : expm1f(v.x);
                v.y = v.y > 0.f ? v.y : expm1f(v.y);
                v.z = v.z > 0.f ? v.z : expm1f(v.z);
                v.w = v.w > 0.f ? v.w : expm1f(v.w);
            }
            uint2 hp, lp;
            hp.x = bf16_hi_pack(v.x, v.y); hp.y = bf16_hi_pack(v.z, v.w);
            lp.x = bf16_lo_pack(v.x, v.y); lp.y = bf16_lo_pack(v.z, v.w);
            *reinterpret_cast<uint2*>(&Xhi[nn * CH_PAD + 4 * k4]) = hp;
            *reinterpret_cast<uint2*>(&Xlo[nn * CH_PAD + 4 * k4]) = lp;
        }
        #pragma unroll
        for (int r = 0; r < 8; r++) {
            int i = tid + r * 128;
            int k = i >> 4, c4 = i & 15;
            float4 w = *reinterpret_cast<const float4*>(
                W2 + (size_t)(kbase + k) * OUT2 + c0 + 4 * c4);
            uint2 hp, lp;
            hp.x = bf16_hi_pack(w.x, w.y); hp.y = bf16_hi_pack(w.z, w.w);
            lp.x = bf16_lo_pack(w.x, w.y); lp.y = bf16_lo_pack(w.z, w.w);
            *reinterpret_cast<uint2*>(&Whi[k * CH_PAD + 4 * c4]) = hp;
            *reinterpret_cast<uint2*>(&Wlo[k * CH_PAD + 4 * c4]) = lp;
        }
        __syncthreads();
        if (do_logits) {
            int nn = tid >> 1, o = tid & 1;
            #pragma unroll 8
            for (int k = 0; k < 64; k++) {
                float xvv = __bfloat162float(Xhi[nn * CH_PAD + k]) +
                            __bfloat162float(Xlo[nn * CH_PAD + k]);
                ls += xvv * swa[2 * (kbase + k) + o];
            }
        }
        #pragma unroll
        for (int ks = 0; ks < 4; ks++) {
            const unsigned koffA = ks * 32;
            const unsigned koffB = ks * 16 * CH_PAD * 2;
            unsigned ah[2][4], al[2][4];
            #pragma unroll
            for (int rg = 0; rg < 2; rg++) {
                LDSM4(ah[rg][0], ah[rg][1], ah[rg][2], ah[rg][3], aAhi[rg] + koffA);
                LDSM4(al[rg][0], al[rg][1], al[rg][2], al[rg][3], aAlo[rg] + koffA);
            }
            #pragma unroll
            for (int ns = 0; ns < 4; ns++) {
                unsigned bh0, bh1, bl0, bl1;
                LDSM2T(bh0, bh1, aBhi + koffB + ns * 16);
                LDSM2T(bl0, bl1, aBlo + koffB + ns * 16);
                #pragma unroll
                for (int rg = 0; rg < 2; rg++) {
                    MMA_BF16(C[rg][ns][0], C[rg][ns][1], C[rg][ns][2], C[rg][ns][3],
                             ah[rg][0], ah[rg][1], ah[rg][2], ah[rg][3], bh0, bh1);
                    MMA_BF16(C[rg][ns][0], C[rg][ns][1], C[rg][ns][2], C[rg][ns][3],
                             ah[rg][0], ah[rg][1], ah[rg][2], ah[rg][3], bl0, bl1);
                    MMA_BF16(C[rg][ns][0], C[rg][ns][1], C[rg][ns][2], C[rg][ns][3],
                             al[rg][0], al[rg][1], al[rg][2], al[rg][3], bh0, bh1);
                }
            }
        }
    }
    #pragma unroll
    for (int rg = 0; rg < 2; rg++) {
        #pragma unroll
        for (int ns = 0; ns < 4; ns++) {
            int col = c0 + wc + ns * 8 + 2 * tg;
            int r0 = n0 + wr + rg * 16 + gq;
            if (r0 < n_nodes)
                *reinterpret_cast<__half2*>(g_h2 + (size_t)r0 * OUT2 + col) =
                    __floats2half2_rn(C[rg][ns][0], C[rg][ns][1]);
            if (r0 + 8 < n_nodes)
                *reinterpret_cast<__half2*>(g_h2 + (size_t)(r0 + 8) * OUT2 + col) =
                    __floats2half2_rn(C[rg][ns][2], C[rg][ns][3]);
        }
    }
    if (do_logits) {
        int nn = tid >> 1, o = tid & 1;
        int g = n0 + nn;
        if (g < n_nodes) {
            if (o == 0) g_as2[g] = ls;
            else        g_ad2[g] = ls;
        }
    }
}

// ============ KA2: gather aggregation, layer 2 (fp16 rows, 64 thr) ==========
__global__ void ka2(int n_nodes, const float* __restrict__ b2,
                    float* __restrict__ out) {
    __shared__ int   ssrc[64];
    __shared__ float sw[64];
    const int d = blockIdx.x;
    const int j = threadIdx.x;   // 64: features 2j, 2j+1
    float add = g_ad2[d];
    float w0 = lrelu_exp(g_as2[d] + add);
    float den = w0;
    float2 acc;
    {
        float2 hv = __half22float2(
            reinterpret_cast<const __half2*>(g_h2 + (size_t)d * OUT2)[j]);
        acc.x = w0 * hv.x; acc.y = w0 * hv.y;
    }
    const int pB = g_off[d], pE = g_off[d + 1];
    for (int p0 = pB; p0 < pE; p0 += 64) {
        int np = min(64, pE - p0);
        __syncthreads();
        if (j < np) {
            int s = g_csrc[p0 + j];
            ssrc[j] = s;
            sw[j] = lrelu_exp(g_as2[s] + add);
        }
        __syncthreads();
        #pragma unroll 8
        for (int e = 0; e < np; e++) {
            int s = ssrc[e];
            float wp = sw[e];
            den += wp;
            float2 hv = __half22float2(
                reinterpret_cast<const __half2*>(g_h2 + (size_t)s * OUT2)[j]);
            acc.x += wp * hv.x; acc.y += wp * hv.y;
        }
    }
    float2 bb = *reinterpret_cast<const float2*>(b2 + 2 * j);
    *reinterpret_cast<float2*>(out + (size_t)d * OUT2 + 2 * j) =
        make_float2(acc.x / den + bb.x, acc.y / den + bb.y);
}

extern "C" void kernel_launch(void* const* d_in, const int* in_sizes, int n_in,
                              void* d_out, int out_size) {
    const float* x    = (const float*)d_in[0];
    const void*  ei   = d_in[1];
    const float* W1   = (const float*)d_in[2];
    const float* as1  = (const float*)d_in[3];
    const float* ad1  = (const float*)d_in[4];
    const float* b1   = (const float*)d_in[5];
    const float* W2   = (const float*)d_in[6];
    const float* as2  = (const float*)d_in[7];
    const float* ad2  = (const float*)d_in[8];
    const float* b2   = (const float*)d_in[9];
    float* out = (float*)d_out;

    const int n_nodes = in_sizes[0] / NF;
    const int E  = in_sizes[1] / 2;

    const int eb = (E + 255) / 256;
    const int nb = (n_nodes + 1023) / 1024;

    static cudaStream_t sA = nullptr, sB = nullptr;
    static cudaEvent_t ev0 = nullptr, evA = nullptr, evB = nullptr;
    static int init_done = 0;
    if (!init_done) {
        cudaFuncSetAttribute(k1_gemm1, cudaFuncAttributeMaxDynamicSharedMemorySize, K1_SMEM);
        cudaFuncSetAttribute(k4_gemm2, cudaFuncAttributeMaxDynamicSharedMemorySize, K4_SMEM);
        cudaStreamCreateWithFlags(&sA, cudaStreamNonBlocking);
        cudaStreamCreateWithFlags(&sB, cudaStreamNonBlocking);
        cudaEventCreateWithFlags(&ev0, cudaEventDisableTiming);
        cudaEventCreateWithFlags(&evA, cudaEventDisableTiming);
        cudaEventCreateWithFlags(&evB, cudaEventDisableTiming);
        init_done = 1;
    }

    dim3 g1((n_nodes + 63) / 64, HH / 64);      // 782 x 4
    dim3 g4((n_nodes + 63) / 64, OUT2 / 64);    // 782 x 2

    // Fork: stream A = CSR build, stream B = attn-vecs + GEMM1
    cudaEventRecord(ev0, 0);
    cudaStreamWaitEvent(sA, ev0, 0);
    cudaStreamWaitEvent(sB, ev0, 0);

    kz<<<nb + 1, 1024, 0, sA>>>((const int*)ei, E, n_nodes);   // 1
    kc2_count<<<eb, 256, 0, sA>>>(ei, E);                      // 2
    kv<<<6, 256, 0, sB>>>(W1, as1, ad1, W2, as2, ad2);         // 3
    k1_gemm1<<<g1, 128, K1_SMEM, sB>>>(x, W1, n_nodes);        // 4  <- profiled slot
    s1_scan<<<nb, 1024, 0, sA>>>(n_nodes);                     // 5
    s2_scan<<<1, 32, 0, sA>>>(nb);                             // 6
    s3_scan<<<nb, 1024, 0, sA>>>(n_nodes, E);                  // 7
    kc3<<<eb, 256, 0, sA>>>(ei, E);                            // 8

    // Join back to the null stream
    cudaEventRecord(evA, sA);
    cudaEventRecord(evB, sB);
    cudaStreamWaitEvent(0, evA, 0);
    cudaStreamWaitEvent(0, evB, 0);

    ka1<<<n_nodes, 128>>>(n_nodes);                            // 9
    k4_gemm2<<<g4, 128, K4_SMEM>>>(W2, b1, n_nodes);           // 10
    ka2<<<n_nodes, 64>>>(n_nodes, b2, out);                    // 11
}

// round 16
// speedup vs baseline: 1.8927x; 1.0425x over previous
#include <cuda_runtime.h>
#include <cuda_bf16.h>
#include <cuda_fp16.h>

#define NMAX   50016
#define EMAX   800000
#define NF     128
#define HH     256
#define OUT2   128
#define NHEADS 4
#define NEG    0.2f

// ---- scratch ----
__device__ __half g_h1[(size_t)NMAX * HH];     // fp16 layer-1 features
__device__ __half g_agg1h[(size_t)NMAX * HH];  // fp16 aggregated layer-1
__device__ __half g_h2[(size_t)NMAX * OUT2];   // fp16 layer-2 features
__device__ float g_as1[NMAX * NHEADS];
__device__ float g_ad1[NMAX * NHEADS];
__device__ float g_as2[NMAX];
__device__ float g_ad2[NMAX];
__device__ float g_va1[NF * 8];
__device__ float g_wa2[HH * 2];
__device__ int   g_is64;
// CSR
__device__ int   g_cnt [NMAX + 1];
__device__ int   g_off [NMAX + 1];
__device__ int   g_cur [NMAX + 1];
__device__ int   g_bsum[64];
__device__ int   g_boff[64];
__device__ int   g_csrc[EMAX];

__device__ __forceinline__ void load_edge(const void* ei, int E, int i,
                                          int& s, int& d) {
    if (g_is64) {
        const long long* p = (const long long*)ei;
        s = (int)p[i]; d = (int)p[(size_t)E + i];
    } else {
        const int* p = (const int*)ei;
        s = p[i]; d = p[E + i];
    }
}

__device__ __forceinline__ float lrelu_exp(float v) {
    v = v > 0.f ? v : NEG * v;
    return __expf(v);
}

#define MMA_BF16(c0,c1,c2,c3,a0,a1,a2,a3,b0,b1) \
    asm("mma.sync.aligned.m16n8k16.row.col.f32.bf16.bf16.f32 " \
        "{%0,%1,%2,%3}, {%4,%5,%6,%7}, {%8,%9}, {%0,%1,%2,%3};" \
        : "+f"(c0), "+f"(c1), "+f"(c2), "+f"(c3) \
        : "r"(a0), "r"(a1), "r"(a2), "r"(a3), "r"(b0), "r"(b1))

#define LDSM4(R0,R1,R2,R3,A) \
    asm volatile("ldmatrix.sync.aligned.m8n8.x4.shared.b16 {%0,%1,%2,%3}, [%4];" \
        : "=r"(R0), "=r"(R1), "=r"(R2), "=r"(R3) : "r"(A))
#define LDSM2T(R0,R1,A) \
    asm volatile("ldmatrix.sync.aligned.m8n8.x2.trans.shared.b16 {%0,%1}, [%2];" \
        : "=r"(R0), "=r"(R1) : "r"(A))

__device__ __forceinline__ unsigned sm_u32(const void* p) {
    return (unsigned)__cvta_generic_to_shared(p);
}

__device__ __forceinline__ unsigned bf16_hi_pack(float a, float b) {
    unsigned ua = (unsigned)__bfloat16_as_ushort(__float2bfloat16(a));
    unsigned ub = (unsigned)__bfloat16_as_ushort(__float2bfloat16(b));
    return ua | (ub << 16);
}
__device__ __forceinline__ unsigned bf16_lo_pack(float a, float b) {
    float ra = a - __bfloat162float(__float2bfloat16(a));
    float rb = b - __bfloat162float(__float2bfloat16(b));
    return bf16_hi_pack(ra, rb);
}

// ============ KZ: dtype probe + zero counts ============
__global__ void kz(const int* ei32, int E, int n) {
    int i = blockIdx.x * 1024 + threadIdx.x;
    if (i <= n) g_cnt[i] = 0;
    if (blockIdx.x == 0) {
        __shared__ int flag;
        if (threadIdx.x == 0) flag = 0;
        __syncthreads();
        for (int j = threadIdx.x; j < 2048; j += 1024) {
            int idx = 2 * j + 1;
            if (idx < 2 * E && ei32[idx] != 0) flag = 1;
        }
        __syncthreads();
        if (threadIdx.x == 0) g_is64 = (flag == 0);
    }
}

// ============ KC2: count in-degrees ============
__global__ void kc2_count(const void* __restrict__ ei, int E) {
    int i = blockIdx.x * blockDim.x + threadIdx.x;
    if (i >= E) return;
    int s, d; load_edge(ei, E, i, s, d);
    atomicAdd(&g_cnt[d], 1);
}

// ============ KV: attention-vector precomputes ============
__global__ void kv(const float* __restrict__ W1, const float* __restrict__ a_s1,
                   const float* __restrict__ a_d1, const float* __restrict__ W2,
                   const float* __restrict__ a_s2, const float* __restrict__ a_d2) {
    int t = blockIdx.x * 256 + threadIdx.x;
    if (t < NF * 8) {
        int k = t >> 3, o = t & 7, h = o & 3;
        const float* a = (o < 4 ? a_s1 : a_d1) + h * 64;
        const float* w = W1 + (size_t)k * HH + h * 64;
        float s = 0.f;
        #pragma unroll 8
        for (int c = 0; c < 64; c++) s += w[c] * a[c];
        g_va1[t] = s;
    } else if (t < NF * 8 + HH * 2) {
        int q = t - NF * 8;
        int k = q >> 1, o = q & 1;
        const float* a = o ? a_d2 : a_s2;
        const float* w = W2 + (size_t)k * OUT2;
        float s = 0.f;
        #pragma unroll 8
        for (int c = 0; c < OUT2; c++) s += w[c] * a[c];
        g_wa2[q] = s;
    }
}

// ==== GEMM geometry: block 64 rows x 128 cols, 64-k chunks, 4 warps ====
// warp tile: 32 rows x 64 cols
#define XPAD  72
#define XSZ   (64 * XPAD)
#define WPAD  136
#define WSZ   (64 * WPAD)

// ============ K1: h1 = x @ W1  (chunked bf16-split MMA) + logits ============
#define K1_SMEM ((2 * XSZ + 2 * WSZ) * 2 + NF * 8 * 4)   // 53248 + 4096
__global__ void __launch_bounds__(128, 3)
k1_gemm1(const float* __restrict__ x, const float* __restrict__ W1,
         int n_nodes) {
    extern __shared__ __nv_bfloat16 smb[];
    __nv_bfloat16* Xhi = smb;
    __nv_bfloat16* Xlo = smb + XSZ;
    __nv_bfloat16* Whi = smb + 2 * XSZ;
    __nv_bfloat16* Wlo = smb + 2 * XSZ + WSZ;
    float* sva = reinterpret_cast<float*>(smb + 2 * XSZ + 2 * WSZ);
    const int n0 = blockIdx.x * 64;
    const int c0 = blockIdx.y * 128;
    const int tid = threadIdx.x;                    // 128
    const bool do_logits = (blockIdx.y == 0);
    if (do_logits) for (int i = tid; i < NF * 8; i += 128) sva[i] = g_va1[i];

    const int wid = tid >> 5, lane = tid & 31;
    const int wr = (wid & 1) * 32;
    const int wc = (wid >> 1) * 64;
    const int gq = lane >> 2, tg = lane & 3;

    unsigned aAhi[2], aAlo[2];
    {
        const int ak = (lane >> 4) * 8;
        #pragma unroll
        for (int rg = 0; rg < 2; rg++) {
            int row = wr + rg * 16 + (lane & 15);
            aAhi[rg] = sm_u32(Xhi + row * XPAD + ak);
            aAlo[rg] = sm_u32(Xlo + row * XPAD + ak);
        }
    }
    unsigned aBhi = sm_u32(Whi + (lane & 15) * WPAD + wc);
    unsigned aBlo = sm_u32(Wlo + (lane & 15) * WPAD + wc);

    float C[2][8][4] = {};
    float s0 = 0.f, s1 = 0.f, s2 = 0.f, s3 = 0.f;
    #pragma unroll
    for (int kc = 0; kc < 2; kc++) {
        const int kbase = kc * 64;
        __syncthreads();
        // stage X chunk (64 rows x 64 k)
        #pragma unroll
        for (int r = 0; r < 8; r++) {
            int i = tid + r * 128;
            int nn = i >> 4, k4 = i & 15;
            int g = n0 + nn;
            float4 v = make_float4(0.f, 0.f, 0.f, 0.f);
            if (g < n_nodes)
                v = *reinterpret_cast<const float4*>(x + (size_t)g * NF + kbase + 4 * k4);
            uint2 hp, lp;
            hp.x = bf16_hi_pack(v.x, v.y); hp.y = bf16_hi_pack(v.z, v.w);
            lp.x = bf16_lo_pack(v.x, v.y); lp.y = bf16_lo_pack(v.z, v.w);
            *reinterpret_cast<uint2*>(&Xhi[nn * XPAD + 4 * k4]) = hp;
            *reinterpret_cast<uint2*>(&Xlo[nn * XPAD + 4 * k4]) = lp;
        }
        // stage W chunk (64 k x 128 cols), k-major
        #pragma unroll
        for (int r = 0; r < 16; r++) {
            int i = tid + r * 128;
            int k = i >> 5, c4 = i & 31;
            float4 w = *reinterpret_cast<const float4*>(
                W1 + (size_t)(kbase + k) * HH + c0 + 4 * c4);
            uint2 hp, lp;
            hp.x = bf16_hi_pack(w.x, w.y); hp.y = bf16_hi_pack(w.z, w.w);
            lp.x = bf16_lo_pack(w.x, w.y); lp.y = bf16_lo_pack(w.z, w.w);
            *reinterpret_cast<uint2*>(&Whi[k * WPAD + 4 * c4]) = hp;
            *reinterpret_cast<uint2*>(&Wlo[k * WPAD + 4 * c4]) = lp;
        }
        __syncthreads();
        if (do_logits) {
            int nn = tid >> 1, o4 = (tid & 1) * 4;
            #pragma unroll 8
            for (int k = 0; k < 64; k++) {
                float xv = __bfloat162float(Xhi[nn * XPAD + k]) +
                           __bfloat162float(Xlo[nn * XPAD + k]);
                const float* sv = sva + (kbase + k) * 8 + o4;
                s0 += xv * sv[0]; s1 += xv * sv[1];
                s2 += xv * sv[2]; s3 += xv * sv[3];
            }
        }
        #pragma unroll
        for (int ks = 0; ks < 4; ks++) {
            const unsigned koffA = ks * 32;
            const unsigned koffB = ks * 16 * WPAD * 2;
            unsigned ah[2][4], al[2][4];
            #pragma unroll
            for (int rg = 0; rg < 2; rg++) {
                LDSM4(ah[rg][0], ah[rg][1], ah[rg][2], ah[rg][3], aAhi[rg] + koffA);
                LDSM4(al[rg][0], al[rg][1], al[rg][2], al[rg][3], aAlo[rg] + koffA);
            }
            #pragma unroll
            for (int ns = 0; ns < 8; ns++) {
                unsigned bh0, bh1, bl0, bl1;
                LDSM2T(bh0, bh1, aBhi + koffB + ns * 16);
                LDSM2T(bl0, bl1, aBlo + koffB + ns * 16);
                #pragma unroll
                for (int rg = 0; rg < 2; rg++) {
                    MMA_BF16(C[rg][ns][0], C[rg][ns][1], C[rg][ns][2], C[rg][ns][3],
                             ah[rg][0], ah[rg][1], ah[rg][2], ah[rg][3], bh0, bh1);
                    MMA_BF16(C[rg][ns][0], C[rg][ns][1], C[rg][ns][2], C[rg][ns][3],
                             ah[rg][0], ah[rg][1], ah[rg][2], ah[rg][3], bl0, bl1);
                    MMA_BF16(C[rg][ns][0], C[rg][ns][1], C[rg][ns][2], C[rg][ns][3],
                             al[rg][0], al[rg][1], al[rg][2], al[rg][3], bh0, bh1);
                }
            }
        }
    }
    #pragma unroll
    for (int rg = 0; rg < 2; rg++) {
        #pragma unroll
        for (int ns = 0; ns < 8; ns++) {
            int col = c0 + wc + ns * 8 + 2 * tg;
            int r0 = n0 + wr + rg * 16 + gq;
            if (r0 < n_nodes)
                *reinterpret_cast<__half2*>(g_h1 + (size_t)r0 * HH + col) =
                    __floats2half2_rn(C[rg][ns][0], C[rg][ns][1]);
            if (r0 + 8 < n_nodes)
                *reinterpret_cast<__half2*>(g_h1 + (size_t)(r0 + 8) * HH + col) =
                    __floats2half2_rn(C[rg][ns][2], C[rg][ns][3]);
        }
    }
    if (do_logits) {
        int nn = tid >> 1, o4 = (tid & 1) * 4;
        int g = n0 + nn;
        if (g < n_nodes) {
            float* dst = (o4 == 0 ? g_as1 : g_ad1) + g * 4;
            *reinterpret_cast<float4*>(dst) = make_float4(s0, s1, s2, s3);
        }
    }
}

// ============ scan ============
__global__ void s1_scan(int n) {
    __shared__ int sd[1024];
    int tid = threadIdx.x;
    int i = blockIdx.x * 1024 + tid;
    int v = (i < n) ? g_cnt[i] : 0;
    sd[tid] = v;
    __syncthreads();
    #pragma unroll
    for (int off = 1; off < 1024; off <<= 1) {
        int t = (tid >= off) ? sd[tid - off] : 0;
        __syncthreads();
        sd[tid] += t;
        __syncthreads();
    }
    if (i < n) g_off[i] = sd[tid] - v;
    if (tid == 1023) g_bsum[blockIdx.x] = sd[1023];
}
__global__ void s2_scan(int nb) {
    if (threadIdx.x == 0) {
        int acc = 0;
        for (int b = 0; b < nb; b++) { int t = g_bsum[b]; g_boff[b] = acc; acc += t; }
    }
}
__global__ void s3_scan(int n, int E) {
    int i = blockIdx.x * 1024 + threadIdx.x;
    if (i < n) {
        int v = g_off[i] + g_boff[blockIdx.x];
        g_off[i] = v;
        g_cur[i] = v;
    }
    if (i == 0) g_off[n] = E;
}

// ============ KC3: CSR fill ============
__global__ void kc3(const void* __restrict__ ei, int E) {
    int i = blockIdx.x * blockDim.x + threadIdx.x;
    if (i >= E) return;
    int s, d; load_edge(ei, E, i, s, d);
    int p = atomicAdd(&g_cur[d], 1);
    g_csrc[p] = s;
}

// ============ KA1: gather aggregation, layer 1 (inline softmax weights) =====
__global__ void ka1(int n_nodes) {
    __shared__ int   ssrc[128];
    __shared__ float sw[128 * 4];
    const int d = blockIdx.x;
    const int j = threadIdx.x;        // 128: features 2j, 2j+1
    const int h = j >> 5;
    const float4 ad4 = *reinterpret_cast<const float4*>(g_ad1 + 4 * d);
    float adh = (h == 0) ? ad4.x : (h == 1) ? ad4.y : (h == 2) ? ad4.z : ad4.w;
    float w0 = lrelu_exp(g_as1[d * NHEADS + h] + adh);
    float den = w0;
    float2 acc;
    {
        float2 hv = __half22float2(
            reinterpret_cast<const __half2*>(g_h1 + (size_t)d * HH)[j]);
        acc.x = w0 * hv.x; acc.y = w0 * hv.y;
    }
    const int pB = g_off[d], pE = g_off[d + 1];
    for (int p0 = pB; p0 < pE; p0 += 128) {
        int np = min(128, pE - p0);
        __syncthreads();
        if (j < np) {
            int s = g_csrc[p0 + j];
            ssrc[j] = s;
            float4 as = *reinterpret_cast<const float4*>(g_as1 + 4 * s);
            sw[4 * j + 0] = lrelu_exp(as.x + ad4.x);
            sw[4 * j + 1] = lrelu_exp(as.y + ad4.y);
            sw[4 * j + 2] = lrelu_exp(as.z + ad4.z);
            sw[4 * j + 3] = lrelu_exp(as.w + ad4.w);
        }
        __syncthreads();
        #pragma unroll 8
        for (int e = 0; e < np; e++) {
            int s = ssrc[e];
            float wp = sw[4 * e + h];
            den += wp;
            float2 hv = __half22float2(
                reinterpret_cast<const __half2*>(g_h1 + (size_t)s * HH)[j]);
            acc.x += wp * hv.x; acc.y += wp * hv.y;
        }
    }
    reinterpret_cast<__half2*>(g_agg1h + (size_t)d * HH)[j] =
        __floats2half2_rn(acc.x / den, acc.y / den);
}

// ============ K4: h2 = elu(agg1+b1) @ W2 (chunked MMA) + layer-2 logits =====
#define K4_SMEM ((2 * XSZ + 2 * WSZ) * 2 + HH * 2 * 4)   // 53248 + 2048
__global__ void __launch_bounds__(128, 3)
k4_gemm2(const float* __restrict__ W2, const float* __restrict__ b1,
         int n_nodes) {
    extern __shared__ __nv_bfloat16 smb[];
    __nv_bfloat16* Xhi = smb;
    __nv_bfloat16* Xlo = smb + XSZ;
    __nv_bfloat16* Whi = smb + 2 * XSZ;
    __nv_bfloat16* Wlo = smb + 2 * XSZ + WSZ;
    float* swa = reinterpret_cast<float*>(smb + 2 * XSZ + 2 * WSZ);
    const int n0 = blockIdx.x * 64;
    const int tid = threadIdx.x;      // 128
    for (int i = tid; i < HH * 2; i += 128) swa[i] = g_wa2[i];

    const int wid = tid >> 5, lane = tid & 31;
    const int wr = (wid & 1) * 32;
    const int wc = (wid >> 1) * 64;
    const int gq = lane >> 2, tg = lane & 3;

    unsigned aAhi[2], aAlo[2];
    {
        const int ak = (lane >> 4) * 8;
        #pragma unroll
        for (int rg = 0; rg < 2; rg++) {
            int row = wr + rg * 16 + (lane & 15);
            aAhi[rg] = sm_u32(Xhi + row * XPAD + ak);
            aAlo[rg] = sm_u32(Xlo + row * XPAD + ak);
        }
    }
    unsigned aBhi = sm_u32(Whi + (lane & 15) * WPAD + wc);
    unsigned aBlo = sm_u32(Wlo + (lane & 15) * WPAD + wc);

    float C[2][8][4] = {};
    float ls = 0.f;
    #pragma unroll
    for (int kc = 0; kc < 4; kc++) {
        const int kbase = kc * 64;
        __syncthreads();
        // stage X chunk: elu(agg1h + b1), hi/lo split
        #pragma unroll
        for (int r = 0; r < 8; r++) {
            int i = tid + r * 128;
            int nn = i >> 4, k4 = i & 15;
            int g = n0 + nn;
            float4 v = make_float4(0.f, 0.f, 0.f, 0.f);
            if (g < n_nodes) {
                int kk = kbase + 4 * k4;
                uint2 raw = *reinterpret_cast<const uint2*>(g_agg1h + (size_t)g * HH + kk);
                float2 f01 = __half22float2(*reinterpret_cast<__half2*>(&raw.x));
                float2 f23 = __half22float2(*reinterpret_cast<__half2*>(&raw.y));
                float4 b = *reinterpret_cast<const float4*>(b1 + kk);
                v.x = f01.x + b.x; v.y = f01.y + b.y;
                v.z = f23.x + b.z; v.w = f23.y + b.w;
                v.x = v.x > 0.f ? v.x : expm1f(v.x);
                v.y = v.y > 0.f ? v.y : expm1f(v.y);
                v.z = v.z > 0.f ? v.z : expm1f(v.z);
                v.w = v.w > 0.f ? v.w : expm1f(v.w);
            }
            uint2 hp, lp;
            hp.x = bf16_hi_pack(v.x, v.y); hp.y = bf16_hi_pack(v.z, v.w);
            lp.x = bf16_lo_pack(v.x, v.y); lp.y = bf16_lo_pack(v.z, v.w);
            *reinterpret_cast<uint2*>(&Xhi[nn * XPAD + 4 * k4]) = hp;
            *reinterpret_cast<uint2*>(&Xlo[nn * XPAD + 4 * k4]) = lp;
        }
        // stage W chunk (64 k x 128 cols), k-major
        #pragma unroll
        for (int r = 0; r < 16; r++) {
            int i = tid + r * 128;
            int k = i >> 5, c4 = i & 31;
            float4 w = *reinterpret_cast<const float4*>(
                W2 + (size_t)(kbase + k) * OUT2 + 4 * c4);
            uint2 hp, lp;
            hp.x = bf16_hi_pack(w.x, w.y); hp.y = bf16_hi_pack(w.z, w.w);
            lp.x = bf16_lo_pack(w.x, w.y); lp.y = bf16_lo_pack(w.z, w.w);
            *reinterpret_cast<uint2*>(&Whi[k * WPAD + 4 * c4]) = hp;
            *reinterpret_cast<uint2*>(&Wlo[k * WPAD + 4 * c4]) = lp;
        }
        __syncthreads();
        // layer-2 logits partial (every block owns distinct rows)
        {
            int nn = tid >> 1, o = tid & 1;
            #pragma unroll 8
            for (int k = 0; k < 64; k++) {
                float xvv = __bfloat162float(Xhi[nn * XPAD + k]) +
                            __bfloat162float(Xlo[nn * XPAD + k]);
                ls += xvv * swa[2 * (kbase + k) + o];
            }
        }
        #pragma unroll
        for (int ks = 0; ks < 4; ks++) {
            const unsigned koffA = ks * 32;
            const unsigned koffB = ks * 16 * WPAD * 2;
            unsigned ah[2][4], al[2][4];
            #pragma unroll
            for (int rg = 0; rg < 2; rg++) {
                LDSM4(ah[rg][0], ah[rg][1], ah[rg][2], ah[rg][3], aAhi[rg] + koffA);
                LDSM4(al[rg][0], al[rg][1], al[rg][2], al[rg][3], aAlo[rg] + koffA);
            }
            #pragma unroll
            for (int ns = 0; ns < 8; ns++) {
                unsigned bh0, bh1, bl0, bl1;
                LDSM2T(bh0, bh1, aBhi + koffB + ns * 16);
                LDSM2T(bl0, bl1, aBlo + koffB + ns * 16);
                #pragma unroll
                for (int rg = 0; rg < 2; rg++) {
                    MMA_BF16(C[rg][ns][0], C[rg][ns][1], C[rg][ns][2], C[rg][ns][3],
                             ah[rg][0], ah[rg][1], ah[rg][2], ah[rg][3], bh0, bh1);
                    MMA_BF16(C[rg][ns][0], C[rg][ns][1], C[rg][ns][2], C[rg][ns][3],
                             ah[rg][0], ah[rg][1], ah[rg][2], ah[rg][3], bl0, bl1);
                    MMA_BF16(C[rg][ns][0], C[rg][ns][1], C[rg][ns][2], C[rg][ns][3],
                             al[rg][0], al[rg][1], al[rg][2], al[rg][3], bh0, bh1);
                }
            }
        }
    }
    #pragma unroll
    for (int rg = 0; rg < 2; rg++) {
        #pragma unroll
        for (int ns = 0; ns < 8; ns++) {
            int col = wc + ns * 8 + 2 * tg;
            int r0 = n0 + wr + rg * 16 + gq;
            if (r0 < n_nodes)
                *reinterpret_cast<__half2*>(g_h2 + (size_t)r0 * OUT2 + col) =
                    __floats2half2_rn(C[rg][ns][0], C[rg][ns][1]);
            if (r0 + 8 < n_nodes)
                *reinterpret_cast<__half2*>(g_h2 + (size_t)(r0 + 8) * OUT2 + col) =
                    __floats2half2_rn(C[rg][ns][2], C[rg][ns][3]);
        }
    }
    {
        int nn = tid >> 1, o = tid & 1;
        int g = n0 + nn;
        if (g < n_nodes) {
            if (o == 0) g_as2[g] = ls;
            else        g_ad2[g] = ls;
        }
    }
}

// ============ KA2: gather aggregation, layer 2 (fp16 rows, 64 thr) ==========
__global__ void ka2(int n_nodes, const float* __restrict__ b2,
                    float* __restrict__ out) {
    __shared__ int   ssrc[64];
    __shared__ float sw[64];
    const int d = blockIdx.x;
    const int j = threadIdx.x;   // 64: features 2j, 2j+1
    float add = g_ad2[d];
    float w0 = lrelu_exp(g_as2[d] + add);
    float den = w0;
    float2 acc;
    {
        float2 hv = __half22float2(
            reinterpret_cast<const __half2*>(g_h2 + (size_t)d * OUT2)[j]);
        acc.x = w0 * hv.x; acc.y = w0 * hv.y;
    }
    const int pB = g_off[d], pE = g_off[d + 1];
    for (int p0 = pB; p0 < pE; p0 += 64) {
        int np = min(64, pE - p0);
        __syncthreads();
        if (j < np) {
            int s = g_csrc[p0 + j];
            ssrc[j] = s;
            sw[j] = lrelu_exp(g_as2[s] + add);
        }
        __syncthreads();
        #pragma unroll 8
        for (int e = 0; e < np; e++) {
            int s = ssrc[e];
            float wp = sw[e];
            den += wp;
            float2 hv = __half22float2(
                reinterpret_cast<const __half2*>(g_h2 + (size_t)s * OUT2)[j]);
            acc.x += wp * hv.x; acc.y += wp * hv.y;
        }
    }
    float2 bb = *reinterpret_cast<const float2*>(b2 + 2 * j);
    *reinterpret_cast<float2*>(out + (size_t)d * OUT2 + 2 * j) =
        make_float2(acc.x / den + bb.x, acc.y / den + bb.y);
}

extern "C" void kernel_launch(void* const* d_in, const int* in_sizes, int n_in,
                              void* d_out, int out_size) {
    const float* x    = (const float*)d_in[0];
    const void*  ei   = d_in[1];
    const float* W1   = (const float*)d_in[2];
    const float* as1  = (const float*)d_in[3];
    const float* ad1  = (const float*)d_in[4];
    const float* b1   = (const float*)d_in[5];
    const float* W2   = (const float*)d_in[6];
    const float* as2  = (const float*)d_in[7];
    const float* ad2  = (const float*)d_in[8];
    const float* b2   = (const float*)d_in[9];
    float* out = (float*)d_out;

    const int n_nodes = in_sizes[0] / NF;
    const int E  = in_sizes[1] / 2;

    const int eb = (E + 255) / 256;
    const int nb = (n_nodes + 1023) / 1024;

    static cudaStream_t sA = nullptr, sB = nullptr;
    static cudaEvent_t ev0 = nullptr, evA = nullptr, evB = nullptr;
    static int init_done = 0;
    if (!init_done) {
        cudaFuncSetAttribute(k1_gemm1, cudaFuncAttributeMaxDynamicSharedMemorySize, K1_SMEM);
        cudaFuncSetAttribute(k4_gemm2, cudaFuncAttributeMaxDynamicSharedMemorySize, K4_SMEM);
        cudaStreamCreateWithFlags(&sA, cudaStreamNonBlocking);
        cudaStreamCreateWithFlags(&sB, cudaStreamNonBlocking);
        cudaEventCreateWithFlags(&ev0, cudaEventDisableTiming);
        cudaEventCreateWithFlags(&evA, cudaEventDisableTiming);
        cudaEventCreateWithFlags(&evB, cudaEventDisableTiming);
        init_done = 1;
    }

    dim3 g1((n_nodes + 63) / 64, HH / 128);     // 782 x 2
    dim3 g4((n_nodes + 63) / 64, 1);            // 782

    // Fork: stream A = CSR build, stream B = attn-vecs + GEMM1
    cudaEventRecord(ev0, 0);
    cudaStreamWaitEvent(sA, ev0, 0);
    cudaStreamWaitEvent(sB, ev0, 0);

    kz<<<nb + 1, 1024, 0, sA>>>((const int*)ei, E, n_nodes);   // 1
    kc2_count<<<eb, 256, 0, sA>>>(ei, E);                      // 2
    kv<<<6, 256, 0, sB>>>(W1, as1, ad1, W2, as2, ad2);         // 3
    k1_gemm1<<<g1, 128, K1_SMEM, sB>>>(x, W1, n_nodes);        // 4  <- profiled slot
    s1_scan<<<nb, 1024, 0, sA>>>(n_nodes);                     // 5
    s2_scan<<<1, 32, 0, sA>>>(nb);                             // 6
    s3_scan<<<nb, 1024, 0, sA>>>(n_nodes, E);                  // 7
    kc3<<<eb, 256, 0, sA>>>(ei, E);                            // 8

    // Join back to the null stream
    cudaEventRecord(evA, sA);
    cudaEventRecord(evB, sB);
    cudaStreamWaitEvent(0, evA, 0);
    cudaStreamWaitEvent(0, evB, 0);

    ka1<<<n_nodes, 128>>>(n_nodes);                            // 9
    k4_gemm2<<<g4, 128, K4_SMEM>>>(W2, b1, n_nodes);           // 10
    ka2<<<n_nodes, 64>>>(n_nodes, b2, out);                    // 11
}